// round 14
// baseline (speedup 1.0000x reference)
#include <cuda_runtime.h>
#include <cuda_fp16.h>
#include <math.h>
#include <stdint.h>

#define Bb   4
#define Tt   8192
#define Dd   512
#define Hh   8
#define DH   64
#define TEE  2048
#define NTOK (Bb*Tt)

// ---------------- scratch ----------------
__device__ __half g_xn[NTOK*Dd];           // LN(x), fp16
__device__ __half g_hs[NTOK*Dd];           // silu(stylized), fp16
__device__ __half g_qkvT[3*Dd*Dd];         // [1536][512] W^T fp16
__device__ __half g_outT[Dd*Dd];           // [512][512]  W^T fp16
__device__ __half g_qs[NTOK*Dd];           // softmaxed q, fp16
__device__ __half g_ek[NTOK*Dd];           // exp(k), fp16
__device__ __half g_vv[NTOK*Dd];           // masked v, fp16
__device__ __half g_y [NTOK*Dd];           // attention out, fp16
__device__ float g_ksum[Bb*Dd];
__device__ float g_attn[Bb*Hh*DH*DH];
__device__ float g_emb[Bb*2*Dd];

// ---------------- helpers ----------------
__device__ __forceinline__ uint32_t smem_u32(const void* p) {
    uint32_t a;
    asm("{ .reg .u64 t; cvta.to.shared.u64 t, %1; cvt.u32.u64 %0, t; }" : "=r"(a) : "l"(p));
    return a;
}
__device__ __forceinline__ void cp16(void* dst, const void* src) {
    uint32_t d;
    asm("{ .reg .u64 t; cvta.to.shared.u64 t, %1; cvt.u32.u64 %0, t; }" : "=r"(d) : "l"(dst));
    asm volatile("cp.async.cg.shared.global [%0], [%1], 16;" :: "r"(d), "l"(src) : "memory");
}
__device__ __forceinline__ void ldsm4(uint32_t* r, uint32_t addr) {
    asm volatile("ldmatrix.sync.aligned.m8n8.x4.shared.b16 {%0,%1,%2,%3}, [%4];"
        : "=r"(r[0]), "=r"(r[1]), "=r"(r[2]), "=r"(r[3]) : "r"(addr));
}
__device__ __forceinline__ void mma_f16(float* c, const uint32_t* a, const uint32_t* b) {
    asm volatile(
        "mma.sync.aligned.m16n8k16.row.col.f32.f16.f16.f32 "
        "{%0,%1,%2,%3}, {%4,%5,%6,%7}, {%8,%9}, {%0,%1,%2,%3};"
        : "+f"(c[0]), "+f"(c[1]), "+f"(c[2]), "+f"(c[3])
        : "r"(a[0]), "r"(a[1]), "r"(a[2]), "r"(a[3]), "r"(b[0]), "r"(b[1]));
}
__device__ __forceinline__ void mma_tf32(float* c, const uint32_t* a, const uint32_t* b) {
    asm volatile(
        "mma.sync.aligned.m16n8k8.row.col.f32.tf32.tf32.f32 "
        "{%0,%1,%2,%3}, {%4,%5,%6,%7}, {%8,%9}, {%0,%1,%2,%3};"
        : "+f"(c[0]), "+f"(c[1]), "+f"(c[2]), "+f"(c[3])
        : "r"(a[0]), "r"(a[1]), "r"(a[2]), "r"(a[3]), "r"(b[0]), "r"(b[1]));
}

// ---------------- zero accumulators + seed emb with bias ----------------
__global__ void zero_k(const float* __restrict__ embB) {
    int i = blockIdx.x * blockDim.x + threadIdx.x;
    if (i < Bb*Dd) g_ksum[i] = 0.f;
    if (i < Bb*Hh*DH*DH) g_attn[i] = 0.f;
    if (i < Bb*2*Dd) g_emb[i] = embB[i & (2*Dd - 1)];
}

// ---------------- weight transpose + fp16 ----------------
__global__ void wconv_k(const float* __restrict__ Wq, const float* __restrict__ Wk,
                        const float* __restrict__ Wv, const float* __restrict__ Wo) {
    __shared__ float t[32][33];
    int mat = blockIdx.z;
    const float* W = mat == 0 ? Wq : mat == 1 ? Wk : mat == 2 ? Wv : Wo;
    int k0 = blockIdx.y * 32, n0 = blockIdx.x * 32;
    int tx = threadIdx.x, ty = threadIdx.y;
    #pragma unroll
    for (int i = 0; i < 4; i++)
        t[ty + i*8][tx] = W[(size_t)(k0 + ty + i*8)*Dd + n0 + tx];
    __syncthreads();
    __half* dst = (mat < 3) ? g_qkvT : g_outT;
    int nbase = (mat < 3) ? mat*Dd : 0;
    #pragma unroll
    for (int i = 0; i < 4; i++) {
        int n = n0 + ty + i*8, k = k0 + tx;
        dst[(size_t)(nbase + n)*Dd + k] = __float2half_rn(t[tx][ty + i*8]);
    }
}

// ---------------- emb partial: silu(emb_chunk) @ W_chunk, atomic add ----------
__global__ void emb_k(const float* __restrict__ emb,
                      const float* __restrict__ W) {
    __shared__ float se[256];
    int b = blockIdx.x, oc = blockIdx.y, ec = blockIdx.z;
    int tid = threadIdx.x;
    if (tid < 128) {
        #pragma unroll
        for (int i = 0; i < 2; i++) {
            float e = emb[b*TEE + ec*256 + tid*2 + i];
            se[tid*2 + i] = e / (1.f + __expf(-e));
        }
    }
    __syncthreads();
    int o = oc*128 + (tid & 127);
    int eh = (tid >> 7) * 128;
    float acc = 0.f;
    #pragma unroll 4
    for (int e = 0; e < 128; e++)
        acc += se[eh + e] * W[(size_t)(ec*256 + eh + e)*(2*Dd) + o];
    atomicAdd(&g_emb[b*2*Dd + o], acc);
}

// ---------------- LN(x) -> g_xn (fp16) ----------------
__global__ void ln_k(const float* __restrict__ x,
                     const float* __restrict__ g,
                     const float* __restrict__ be) {
    int tok = blockIdx.x, tid = threadIdx.x;
    float4 v = ((const float4*)(x + (size_t)tok*Dd))[tid];
    float s = v.x + v.y + v.z + v.w;
    __shared__ float r1[4], r2[4];
    for (int o = 16; o; o >>= 1) s += __shfl_xor_sync(0xffffffffu, s, o);
    if ((tid & 31) == 0) r1[tid >> 5] = s;
    __syncthreads();
    float mu = (r1[0] + r1[1] + r1[2] + r1[3]) * (1.f / Dd);
    float a = v.x - mu, b = v.y - mu, c = v.z - mu, d = v.w - mu;
    float ss = a*a + b*b + c*c + d*d;
    for (int o = 16; o; o >>= 1) ss += __shfl_xor_sync(0xffffffffu, ss, o);
    if ((tid & 31) == 0) r2[tid >> 5] = ss;
    __syncthreads();
    float var = (r2[0] + r2[1] + r2[2] + r2[3]) * (1.f / Dd);
    float rs = rsqrtf(var + 1e-5f);
    float4 gg = ((const float4*)g)[tid], bb = ((const float4*)be)[tid];
    __half2* ph = (__half2*)(g_xn + (size_t)tok*Dd);
    ph[tid*2]   = __halves2half2(__float2half_rn(a*rs*gg.x + bb.x),
                                 __float2half_rn(b*rs*gg.y + bb.y));
    ph[tid*2+1] = __halves2half2(__float2half_rn(c*rs*gg.z + bb.z),
                                 __float2half_rn(d*rs*gg.w + bb.w));
}

// ------- persistent fp16 HMMA GEMM, cross-tile pipelined chunk stream -------
#define AROW 72
#define STG_A (128*AROW)
#define STG_B (128*AROW)
#define STAGE_H (STG_A + STG_B)
#define SMEM_BYTES (3*STAGE_H*2)           // 110592 B -> 2 CTAs/SM
#define NPERSIST 296                       // 2 CTAs/SM x 148 SMs

__device__ __forceinline__ void copy_stage(__half* smh, int st, int kc,
    const __half* __restrict__ Ag, const __half* __restrict__ Bg,
    int m0, int n0, int tid)
{
    __half* A = smh + st*STAGE_H;
    __half* B = A + STG_A;
    #pragma unroll
    for (int i = 0; i < 4; i++) {
        int s = tid + i*256;
        int r = s >> 3, c8 = s & 7;
        cp16(A + r*AROW + c8*8, Ag + (size_t)(m0 + r)*Dd + kc*64 + c8*8);
    }
    #pragma unroll
    for (int i = 0; i < 4; i++) {
        int s = tid + i*256;
        int r = s >> 3, c8 = s & 7;
        cp16(B + r*AROW + c8*8, Bg + (size_t)(n0 + r)*Dd + kc*64 + c8*8);
    }
    asm volatile("cp.async.commit_group;" ::: "memory");
}

__global__ __launch_bounds__(256, 2) void gemm_k(
    int mode,                       // 0 = QKV, 1 = OUT
    int tilesX,                     // n-blocks
    int nTiles,                     // tilesX * m-blocks
    const float* __restrict__ b0, const float* __restrict__ b1, const float* __restrict__ b2,
    const float* __restrict__ mask, const float* __restrict__ xres, float* __restrict__ outp)
{
    extern __shared__ __half smh[];
    uint32_t smb = smem_u32(smh);
    int tid = threadIdx.x;
    int lane = tid & 31, w = tid >> 5;
    int g = lane >> 2, cq = lane & 3;
    int wm = w >> 1, wn = w & 1;
    int mBase = wm*32, nBase = wn*64;

    const __half* Ag = mode ? g_hs : g_xn;
    const __half* Bg = mode ? g_outT : g_qkvT;

    uint32_t aoff[2], boff[4];
    {
        int ar = lane & 15;
        int ac = (lane >> 4) * 8;
        #pragma unroll
        for (int mt = 0; mt < 2; mt++)
            aoff[mt] = (uint32_t)(((mBase + mt*16 + ar)*AROW + ac) * 2);
        int br = ((lane >> 4) << 3) | (lane & 7);
        int bc = ((lane >> 3) & 1) * 8;
        #pragma unroll
        for (int p = 0; p < 4; p++)
            boff[p] = (uint32_t)(((nBase + p*16 + br)*AROW + bc) * 2 + STG_A*2);
    }

    // local tile count for this CTA; flat chunk stream c = i*8 + kc
    int ntl = (nTiles - (int)blockIdx.x + (int)gridDim.x - 1) / (int)gridDim.x;
    if (ntl <= 0) return;
    int C = ntl * 8;

    // chunk issue helper (inline): chunk c -> tile (c>>3), kc (c&7)
    #define ISSUE(c) do {                                                        \
        int _i = (c) >> 3, _kc = (c) & 7;                                        \
        int _tile = (int)blockIdx.x + _i * (int)gridDim.x;                       \
        int _m0 = (_tile / tilesX) * 128;                                        \
        int _n0 = (_tile % tilesX) * 128;                                        \
        copy_stage(smh, (c) % 3, _kc, Ag, Bg, _m0, _n0, tid);                    \
    } while (0)

    float acc[2][8][4];
    #pragma unroll
    for (int i = 0; i < 2; i++)
        #pragma unroll
        for (int j = 0; j < 8; j++)
            #pragma unroll
            for (int r = 0; r < 4; r++) acc[i][j][r] = 0.f;

    ISSUE(0);
    ISSUE(1);

    for (int c = 0; c < C; c++) {
        if (c + 2 < C) ISSUE(c + 2);
        if (c + 2 < C)      asm volatile("cp.async.wait_group 2;" ::: "memory");
        else if (c + 1 < C) asm volatile("cp.async.wait_group 1;" ::: "memory");
        else                asm volatile("cp.async.wait_group 0;" ::: "memory");
        __syncthreads();

        uint32_t stageB = smb + (uint32_t)((c % 3)*STAGE_H*2);
        #pragma unroll
        for (int k16 = 0; k16 < 4; k16++) {
            uint32_t kb = (uint32_t)(k16*32);
            uint32_t a[2][4], bb[4][4];
            #pragma unroll
            for (int mt = 0; mt < 2; mt++) ldsm4(a[mt], stageB + aoff[mt] + kb);
            #pragma unroll
            for (int p = 0; p < 4; p++)    ldsm4(bb[p], stageB + boff[p] + kb);
            #pragma unroll
            for (int mt = 0; mt < 2; mt++)
                #pragma unroll
                for (int p = 0; p < 4; p++) {
                    mma_f16(acc[mt][2*p],   a[mt], &bb[p][0]);
                    mma_f16(acc[mt][2*p+1], a[mt], &bb[p][2]);
                }
        }
        __syncthreads();

        if ((c & 7) != 7) continue;

        // ---------------- register epilogue for finished tile ----------------
        int tile = (int)blockIdx.x + (c >> 3) * (int)gridDim.x;
        int m0 = (tile / tilesX) * 128;
        int n0 = (tile % tilesX) * 128;
        int region = n0 >> 9;
        const float* bia = (mode == 1) ? b0 : (region == 0 ? b0 : (region == 1 ? b1 : b2));
        int cbase = ((mode == 1) ? n0 : (n0 & 511)) + nBase + cq*2;
        float blo[8], bhi[8];
        #pragma unroll
        for (int nt = 0; nt < 8; nt++) { blo[nt] = bia[cbase + nt*8]; bhi[nt] = bia[cbase + nt*8 + 1]; }

        if (mode == 1) {
            #pragma unroll
            for (int mt = 0; mt < 2; mt++)
                #pragma unroll
                for (int rh = 0; rh < 2; rh++) {
                    int m = m0 + mBase + mt*16 + g + rh*8;
                    #pragma unroll
                    for (int nt = 0; nt < 8; nt++) {
                        size_t off = (size_t)m*Dd + n0 + nBase + nt*8 + cq*2;
                        float2 xr = *(const float2*)(xres + off);
                        float2 o = make_float2(acc[mt][nt][2*rh]   + blo[nt] + xr.x,
                                               acc[mt][nt][2*rh+1] + bhi[nt] + xr.y);
                        *(float2*)(outp + off) = o;
                    }
                }
        } else if (region == 0) {
            #pragma unroll
            for (int mt = 0; mt < 2; mt++)
                #pragma unroll
                for (int rh = 0; rh < 2; rh++) {
                    int m = m0 + mBase + mt*16 + g + rh*8;
                    float v0[8], v1[8];
                    float mx = -1e30f;
                    #pragma unroll
                    for (int nt = 0; nt < 8; nt++) {
                        v0[nt] = acc[mt][nt][2*rh]   + blo[nt];
                        v1[nt] = acc[mt][nt][2*rh+1] + bhi[nt];
                        mx = fmaxf(mx, fmaxf(v0[nt], v1[nt]));
                    }
                    mx = fmaxf(mx, __shfl_xor_sync(0xffffffffu, mx, 1));
                    mx = fmaxf(mx, __shfl_xor_sync(0xffffffffu, mx, 2));
                    float s = 0.f;
                    #pragma unroll
                    for (int nt = 0; nt < 8; nt++) {
                        v0[nt] = __expf(v0[nt] - mx); v1[nt] = __expf(v1[nt] - mx);
                        s += v0[nt] + v1[nt];
                    }
                    s += __shfl_xor_sync(0xffffffffu, s, 1);
                    s += __shfl_xor_sync(0xffffffffu, s, 2);
                    float inv = 1.f / s;
                    #pragma unroll
                    for (int nt = 0; nt < 8; nt++)
                        *(__half2*)(g_qs + (size_t)m*Dd + cbase + nt*8) =
                            __floats2half2_rn(v0[nt]*inv, v1[nt]*inv);
                }
        } else if (region == 1) {
            float cs0[8] = {}, cs1[8] = {};
            #pragma unroll
            for (int mt = 0; mt < 2; mt++)
                #pragma unroll
                for (int rh = 0; rh < 2; rh++) {
                    int m = m0 + mBase + mt*16 + g + rh*8;
                    float madd = (1.f - mask[m]) * (-1e6f);
                    #pragma unroll
                    for (int nt = 0; nt < 8; nt++) {
                        float e0 = __expf(acc[mt][nt][2*rh]   + blo[nt] + madd);
                        float e1 = __expf(acc[mt][nt][2*rh+1] + bhi[nt] + madd);
                        __half2 h2 = __floats2half2_rn(e0, e1);
                        *(__half2*)(g_ek + (size_t)m*Dd + cbase + nt*8) = h2;
                        float2 hf = __half22float2(h2);
                        cs0[nt] += hf.x; cs1[nt] += hf.y;
                    }
                }
            #pragma unroll
            for (int o = 4; o <= 16; o <<= 1)
                #pragma unroll
                for (int nt = 0; nt < 8; nt++) {
                    cs0[nt] += __shfl_xor_sync(0xffffffffu, cs0[nt], o);
                    cs1[nt] += __shfl_xor_sync(0xffffffffu, cs1[nt], o);
                }
            if (lane < 4) {
                int batch = m0 >> 13;
                #pragma unroll
                for (int nt = 0; nt < 8; nt++) {
                    atomicAdd(&g_ksum[batch*Dd + cbase + nt*8],     cs0[nt]);
                    atomicAdd(&g_ksum[batch*Dd + cbase + nt*8 + 1], cs1[nt]);
                }
            }
        } else {
            #pragma unroll
            for (int mt = 0; mt < 2; mt++)
                #pragma unroll
                for (int rh = 0; rh < 2; rh++) {
                    int m = m0 + mBase + mt*16 + g + rh*8;
                    float mv = mask[m];
                    #pragma unroll
                    for (int nt = 0; nt < 8; nt++)
                        *(__half2*)(g_vv + (size_t)m*Dd + cbase + nt*8) =
                            __floats2half2_rn((acc[mt][nt][2*rh]   + blo[nt])*mv,
                                              (acc[mt][nt][2*rh+1] + bhi[nt])*mv);
                }
        }

        // reset accumulators for next tile
        #pragma unroll
        for (int i = 0; i < 2; i++)
            #pragma unroll
            for (int j = 0; j < 8; j++)
                #pragma unroll
                for (int r = 0; r < 4; r++) acc[i][j][r] = 0.f;
    }
    #undef ISSUE
}

// ---------------- KV state (tf32 tensor, fp16 inputs) ----------------
__global__ __launch_bounds__(128) void kv_k() {
    __shared__ float Es[64][72];
    __shared__ float Vs[64][72];
    int bh = blockIdx.x; int b = bh >> 3; int h = bh & 7;
    int t0 = b*Tt + blockIdx.y * 512;
    int tid = threadIdx.x;
    int lane = tid & 31, w = tid >> 5;
    int g = lane >> 2, cq = lane & 3;
    int mBase = w * 16;

    float acc[8][4];
    #pragma unroll
    for (int i = 0; i < 8; i++)
        #pragma unroll
        for (int r = 0; r < 4; r++) acc[i][r] = 0.f;

    for (int tile = 0; tile < 8; tile++) {
        #pragma unroll
        for (int i = 0; i < 8; i++) {
            int s = tid + i*128;
            int r = s >> 4, c4 = s & 15;
            size_t base = (size_t)(t0 + tile*64 + r)*Dd + h*DH + c4*4;
            const __half2* pe = (const __half2*)(g_ek + base);
            const __half2* pv = (const __half2*)(g_vv + base);
            float2 e0 = __half22float2(pe[0]), e1 = __half22float2(pe[1]);
            float2 v0 = __half22float2(pv[0]), v1 = __half22float2(pv[1]);
            *(float4*)&Es[r][c4*4] = make_float4(e0.x, e0.y, e1.x, e1.y);
            *(float4*)&Vs[r][c4*4] = make_float4(v0.x, v0.y, v1.x, v1.y);
        }
        __syncthreads();
        #pragma unroll
        for (int k8 = 0; k8 < 8; k8++) {
            int kk = k8*8;
            uint32_t a[4], bfr[8][2];
            a[0] = __float_as_uint(Es[kk+cq][mBase+g]);
            a[1] = __float_as_uint(Es[kk+cq][mBase+g+8]);
            a[2] = __float_as_uint(Es[kk+cq+4][mBase+g]);
            a[3] = __float_as_uint(Es[kk+cq+4][mBase+g+8]);
            #pragma unroll
            for (int nt = 0; nt < 8; nt++) {
                bfr[nt][0] = __float_as_uint(Vs[kk+cq][nt*8+g]);
                bfr[nt][1] = __float_as_uint(Vs[kk+cq+4][nt*8+g]);
            }
            #pragma unroll
            for (int nt = 0; nt < 8; nt++)
                mma_tf32(acc[nt], a, bfr[nt]);
        }
        __syncthreads();
    }
    float* A = g_attn + (size_t)bh*DH*DH;
    #pragma unroll
    for (int nt = 0; nt < 8; nt++) {
        int n = nt*8 + cq*2;
        atomicAdd(&A[(mBase+g)*DH + n],     acc[nt][0]);
        atomicAdd(&A[(mBase+g)*DH + n+1],   acc[nt][1]);
        atomicAdd(&A[(mBase+g+8)*DH + n],   acc[nt][2]);
        atomicAdd(&A[(mBase+g+8)*DH + n+1], acc[nt][3]);
    }
}

// ---------------- y = q_h @ (attn_h / ksum) (tf32 tensor, fp16 in/out) --------
__global__ __launch_bounds__(128) void y_k() {
    __shared__ float Qs[64][68];
    __shared__ float Ahs[64][72];
    int bh = blockIdx.x; int b = bh >> 3; int h = bh & 7;
    int t0 = b*Tt + blockIdx.y * 64;
    int tid = threadIdx.x;
    int lane = tid & 31, w = tid >> 5;
    int g = lane >> 2, cq = lane & 3;
    int mBase = w * 16;

    {
        const float* A  = g_attn + (size_t)bh*DH*DH;
        const float* ks = g_ksum + b*Dd + h*DH;
        #pragma unroll
        for (int i = 0; i < 8; i++) {
            int s = tid + i*128;
            int r = s >> 4, c4 = s & 15;
            float rk = 1.f / ks[r];
            float4 a = *(const float4*)(A + r*DH + c4*4);
            a.x *= rk; a.y *= rk; a.z *= rk; a.w *= rk;
            *(float4*)&Ahs[r][c4*4] = a;
            const __half2* pq = (const __half2*)(g_qs + (size_t)(t0 + r)*Dd + h*DH + c4*4);
            float2 q0 = __half22float2(pq[0]), q1 = __half22float2(pq[1]);
            *(float4*)&Qs[r][c4*4] = make_float4(q0.x, q0.y, q1.x, q1.y);
        }
    }
    __syncthreads();

    float acc[8][4];
    #pragma unroll
    for (int i = 0; i < 8; i++)
        #pragma unroll
        for (int r = 0; r < 4; r++) acc[i][r] = 0.f;

    #pragma unroll
    for (int k8 = 0; k8 < 8; k8++) {
        int kk = k8*8;
        uint32_t a[4], bfr[8][2];
        a[0] = __float_as_uint(Qs[mBase+g][kk+cq]);
        a[1] = __float_as_uint(Qs[mBase+g+8][kk+cq]);
        a[2] = __float_as_uint(Qs[mBase+g][kk+cq+4]);
        a[3] = __float_as_uint(Qs[mBase+g+8][kk+cq+4]);
        #pragma unroll
        for (int nt = 0; nt < 8; nt++) {
            bfr[nt][0] = __float_as_uint(Ahs[kk+cq][nt*8+g]);
            bfr[nt][1] = __float_as_uint(Ahs[kk+cq+4][nt*8+g]);
        }
        #pragma unroll
        for (int nt = 0; nt < 8; nt++)
            mma_tf32(acc[nt], a, bfr[nt]);
    }

    #pragma unroll
    for (int nt = 0; nt < 8; nt++) {
        int n = h*DH + nt*8 + cq*2;
        size_t r0 = (size_t)(t0 + mBase + g)*Dd + n;
        size_t r1 = (size_t)(t0 + mBase + g + 8)*Dd + n;
        *(__half2*)(g_y + r0) = __floats2half2_rn(acc[nt][0], acc[nt][1]);
        *(__half2*)(g_y + r1) = __floats2half2_rn(acc[nt][2], acc[nt][3]);
    }
}

// ---------------- stylize + silu -> g_hs (fp16 in/out) ----------------
__global__ void style_k(const float* __restrict__ g2, const float* __restrict__ b2) {
    int tok = blockIdx.x, tid = threadIdx.x;
    int b = tok >> 13;
    const __half2* py = (const __half2*)(g_y + (size_t)tok*Dd);
    float2 y01 = __half22float2(py[tid*2]);
    float2 y23 = __half22float2(py[tid*2+1]);
    float s = y01.x + y01.y + y23.x + y23.y;
    __shared__ float r1[4], r2[4];
    for (int o = 16; o; o >>= 1) s += __shfl_xor_sync(0xffffffffu, s, o);
    if ((tid & 31) == 0) r1[tid >> 5] = s;
    __syncthreads();
    float mu = (r1[0] + r1[1] + r1[2] + r1[3]) * (1.f / Dd);
    float a = y01.x - mu, bb_ = y01.y - mu, c = y23.x - mu, d = y23.y - mu;
    float ss = a*a + bb_*bb_ + c*c + d*d;
    for (int o = 16; o; o >>= 1) ss += __shfl_xor_sync(0xffffffffu, ss, o);
    if ((tid & 31) == 0) r2[tid >> 5] = ss;
    __syncthreads();
    float var = (r2[0] + r2[1] + r2[2] + r2[3]) * (1.f / Dd);
    float rs = rsqrtf(var + 1e-5f);
    float4 gg = ((const float4*)g2)[tid], bt = ((const float4*)b2)[tid];
    float4 sc = ((const float4*)(g_emb + b*2*Dd))[tid];
    float4 sh = ((const float4*)(g_emb + b*2*Dd + Dd))[tid];
    float h0 = (a  *rs*gg.x + bt.x)*(1.f + sc.x) + sh.x;
    float h1 = (bb_*rs*gg.y + bt.y)*(1.f + sc.y) + sh.y;
    float h2 = (c  *rs*gg.z + bt.z)*(1.f + sc.z) + sh.z;
    float h3 = (d  *rs*gg.w + bt.w)*(1.f + sc.w) + sh.w;
    h0 = h0 / (1.f + __expf(-h0));
    h1 = h1 / (1.f + __expf(-h1));
    h2 = h2 / (1.f + __expf(-h2));
    h3 = h3 / (1.f + __expf(-h3));
    __half2* ph = (__half2*)(g_hs + (size_t)tok*Dd);
    ph[tid*2]   = __halves2half2(__float2half_rn(h0), __float2half_rn(h1));
    ph[tid*2+1] = __halves2half2(__float2half_rn(h2), __float2half_rn(h3));
}

// ---------------- launch ----------------
extern "C" void kernel_launch(void* const* d_in, const int* in_sizes, int n_in,
                              void* d_out, int out_size) {
    const float* x     = (const float*)d_in[0];
    const float* emb   = (const float*)d_in[1];
    const float* mask  = (const float*)d_in[2];
    const float* gamma = (const float*)d_in[3];
    const float* beta  = (const float*)d_in[4];
    const float* Wq    = (const float*)d_in[5];
    const float* bq    = (const float*)d_in[6];
    const float* Wk    = (const float*)d_in[7];
    const float* bk    = (const float*)d_in[8];
    const float* Wv    = (const float*)d_in[9];
    const float* bv    = (const float*)d_in[10];
    const float* embW  = (const float*)d_in[11];
    const float* embB  = (const float*)d_in[12];
    const float* g2    = (const float*)d_in[13];
    const float* b2    = (const float*)d_in[14];
    const float* outW  = (const float*)d_in[15];
    const float* outB  = (const float*)d_in[16];
    float* out = (float*)d_out;

    static int inited = 0;
    static cudaStream_t s2;
    static cudaEvent_t ev0, ev1;
    if (!inited) {
        cudaFuncSetAttribute(gemm_k, cudaFuncAttributeMaxDynamicSharedMemorySize, SMEM_BYTES);
        cudaStreamCreateWithFlags(&s2, cudaStreamNonBlocking);
        cudaEventCreateWithFlags(&ev0, cudaEventDisableTiming);
        cudaEventCreateWithFlags(&ev1, cudaEventDisableTiming);
        inited = 1;
    }

    // fork: {wconv, emb} on s2 || {ln} on main; join before QKV GEMM
    zero_k <<<512, 256>>>(embB);
    cudaEventRecord(ev0, 0);
    cudaStreamWaitEvent(s2, ev0, 0);
    wconv_k<<<dim3(16, 16, 4), dim3(32, 8), 0, s2>>>(Wq, Wk, Wv, outW);
    emb_k  <<<dim3(Bb, 8, 8), 256, 0, s2>>>(emb, embW);
    cudaEventRecord(ev1, s2);
    ln_k   <<<NTOK, 128>>>(x, gamma, beta);
    cudaStreamWaitEvent(0, ev1, 0);

    gemm_k <<<NPERSIST, 256, SMEM_BYTES>>>(0, 12, 12*(NTOK/128), bq, bk, bv, mask, nullptr, nullptr);
    kv_k   <<<dim3(Bb*Hh, 16), 128>>>();
    y_k    <<<dim3(Bb*Hh, Tt/64), 128>>>();
    style_k<<<NTOK, 128>>>(g2, b2);
    gemm_k <<<NPERSIST, 256, SMEM_BYTES>>>(1, 4, 4*(NTOK/128), outB, nullptr, nullptr, nullptr, x, out);
}

// round 15
// speedup vs baseline: 1.0395x; 1.0395x over previous
#include <cuda_runtime.h>
#include <cuda_fp16.h>
#include <math.h>
#include <stdint.h>

#define Bb   4
#define Tt   8192
#define Dd   512
#define Hh   8
#define DH   64
#define TEE  2048
#define NTOK (Bb*Tt)

// ---------------- scratch ----------------
__device__ __half g_xn[NTOK*Dd];           // LN(x), fp16
__device__ __half g_hs[NTOK*Dd];           // silu(stylized), fp16
__device__ __half g_qkvT[3*Dd*Dd];         // [1536][512] W^T fp16
__device__ __half g_outT[Dd*Dd];           // [512][512]  W^T fp16
__device__ __half g_qs[NTOK*Dd];           // softmaxed q, fp16
__device__ __half g_ek[NTOK*Dd];           // exp(k), fp16
__device__ __half g_vv[NTOK*Dd];           // masked v, fp16
__device__ __half g_y [NTOK*Dd];           // attention out, fp16
__device__ float g_ksum[Bb*Dd];
__device__ float g_attn[Bb*Hh*DH*DH];
__device__ float g_emb[Bb*2*Dd];

// ---------------- helpers ----------------
__device__ __forceinline__ uint32_t smem_u32(const void* p) {
    uint32_t a;
    asm("{ .reg .u64 t; cvta.to.shared.u64 t, %1; cvt.u32.u64 %0, t; }" : "=r"(a) : "l"(p));
    return a;
}
__device__ __forceinline__ void cp16(void* dst, const void* src) {
    uint32_t d;
    asm("{ .reg .u64 t; cvta.to.shared.u64 t, %1; cvt.u32.u64 %0, t; }" : "=r"(d) : "l"(dst));
    asm volatile("cp.async.cg.shared.global [%0], [%1], 16;" :: "r"(d), "l"(src) : "memory");
}
__device__ __forceinline__ void ldsm4(uint32_t* r, uint32_t addr) {
    asm volatile("ldmatrix.sync.aligned.m8n8.x4.shared.b16 {%0,%1,%2,%3}, [%4];"
        : "=r"(r[0]), "=r"(r[1]), "=r"(r[2]), "=r"(r[3]) : "r"(addr));
}
__device__ __forceinline__ void mma_f16(float* c, const uint32_t* a, const uint32_t* b) {
    asm volatile(
        "mma.sync.aligned.m16n8k16.row.col.f32.f16.f16.f32 "
        "{%0,%1,%2,%3}, {%4,%5,%6,%7}, {%8,%9}, {%0,%1,%2,%3};"
        : "+f"(c[0]), "+f"(c[1]), "+f"(c[2]), "+f"(c[3])
        : "r"(a[0]), "r"(a[1]), "r"(a[2]), "r"(a[3]), "r"(b[0]), "r"(b[1]));
}
__device__ __forceinline__ void mma_tf32(float* c, const uint32_t* a, const uint32_t* b) {
    asm volatile(
        "mma.sync.aligned.m16n8k8.row.col.f32.tf32.tf32.f32 "
        "{%0,%1,%2,%3}, {%4,%5,%6,%7}, {%8,%9}, {%0,%1,%2,%3};"
        : "+f"(c[0]), "+f"(c[1]), "+f"(c[2]), "+f"(c[3])
        : "r"(a[0]), "r"(a[1]), "r"(a[2]), "r"(a[3]), "r"(b[0]), "r"(b[1]));
}

// ---------------- zero accumulators + seed emb with bias ----------------
__global__ void zero_k(const float* __restrict__ embB) {
    int i = blockIdx.x * blockDim.x + threadIdx.x;
    if (i < Bb*Dd) g_ksum[i] = 0.f;
    if (i < Bb*Hh*DH*DH) g_attn[i] = 0.f;
    if (i < Bb*2*Dd) g_emb[i] = embB[i & (2*Dd - 1)];
}

// ---------------- weight transpose + fp16 ----------------
__global__ void wconv_k(const float* __restrict__ Wq, const float* __restrict__ Wk,
                        const float* __restrict__ Wv, const float* __restrict__ Wo) {
    __shared__ float t[32][33];
    int mat = blockIdx.z;
    const float* W = mat == 0 ? Wq : mat == 1 ? Wk : mat == 2 ? Wv : Wo;
    int k0 = blockIdx.y * 32, n0 = blockIdx.x * 32;
    int tx = threadIdx.x, ty = threadIdx.y;
    #pragma unroll
    for (int i = 0; i < 4; i++)
        t[ty + i*8][tx] = W[(size_t)(k0 + ty + i*8)*Dd + n0 + tx];
    __syncthreads();
    __half* dst = (mat < 3) ? g_qkvT : g_outT;
    int nbase = (mat < 3) ? mat*Dd : 0;
    #pragma unroll
    for (int i = 0; i < 4; i++) {
        int n = n0 + ty + i*8, k = k0 + tx;
        dst[(size_t)(nbase + n)*Dd + k] = __float2half_rn(t[tx][ty + i*8]);
    }
}

// ---------------- emb partial: silu(emb_chunk) @ W_chunk, atomic add ----------
__global__ void emb_k(const float* __restrict__ emb,
                      const float* __restrict__ W) {
    __shared__ float se[256];
    int b = blockIdx.x, oc = blockIdx.y, ec = blockIdx.z;
    int tid = threadIdx.x;
    if (tid < 128) {
        #pragma unroll
        for (int i = 0; i < 2; i++) {
            float e = emb[b*TEE + ec*256 + tid*2 + i];
            se[tid*2 + i] = e / (1.f + __expf(-e));
        }
    }
    __syncthreads();
    int o = oc*128 + (tid & 127);
    int eh = (tid >> 7) * 128;
    float acc = 0.f;
    #pragma unroll 4
    for (int e = 0; e < 128; e++)
        acc += se[eh + e] * W[(size_t)(ec*256 + eh + e)*(2*Dd) + o];
    atomicAdd(&g_emb[b*2*Dd + o], acc);
}

// ---------------- LN(x) -> g_xn (fp16) ----------------
__global__ void ln_k(const float* __restrict__ x,
                     const float* __restrict__ g,
                     const float* __restrict__ be) {
    int tok = blockIdx.x, tid = threadIdx.x;
    float4 v = ((const float4*)(x + (size_t)tok*Dd))[tid];
    float s = v.x + v.y + v.z + v.w;
    __shared__ float r1[4], r2[4];
    for (int o = 16; o; o >>= 1) s += __shfl_xor_sync(0xffffffffu, s, o);
    if ((tid & 31) == 0) r1[tid >> 5] = s;
    __syncthreads();
    float mu = (r1[0] + r1[1] + r1[2] + r1[3]) * (1.f / Dd);
    float a = v.x - mu, b = v.y - mu, c = v.z - mu, d = v.w - mu;
    float ss = a*a + b*b + c*c + d*d;
    for (int o = 16; o; o >>= 1) ss += __shfl_xor_sync(0xffffffffu, ss, o);
    if ((tid & 31) == 0) r2[tid >> 5] = ss;
    __syncthreads();
    float var = (r2[0] + r2[1] + r2[2] + r2[3]) * (1.f / Dd);
    float rs = rsqrtf(var + 1e-5f);
    float4 gg = ((const float4*)g)[tid], bb = ((const float4*)be)[tid];
    __half2* ph = (__half2*)(g_xn + (size_t)tok*Dd);
    ph[tid*2]   = __halves2half2(__float2half_rn(a*rs*gg.x + bb.x),
                                 __float2half_rn(b*rs*gg.y + bb.y));
    ph[tid*2+1] = __halves2half2(__float2half_rn(c*rs*gg.z + bb.z),
                                 __float2half_rn(d*rs*gg.w + bb.w));
}

// ---------------- fp16 HMMA GEMM: BM=128, BN=128, BK=64, 2 CTAs/SM ----------
#define AROW 72
#define STG_A (128*AROW)
#define STG_B (128*AROW)
#define STAGE_H (STG_A + STG_B)
#define SMEM_BYTES (3*STAGE_H*2)           // 110592 B -> 2 CTAs/SM

__device__ __forceinline__ void copy_stage(__half* smh, int st, int kc,
    const __half* __restrict__ Ag, const __half* __restrict__ Bg,
    int m0, int n0, int tid)
{
    __half* A = smh + st*STAGE_H;
    __half* B = A + STG_A;
    #pragma unroll
    for (int i = 0; i < 4; i++) {
        int s = tid + i*256;
        int r = s >> 3, c8 = s & 7;
        cp16(A + r*AROW + c8*8, Ag + (size_t)(m0 + r)*Dd + kc*64 + c8*8);
    }
    #pragma unroll
    for (int i = 0; i < 4; i++) {
        int s = tid + i*256;
        int r = s >> 3, c8 = s & 7;
        cp16(B + r*AROW + c8*8, Bg + (size_t)(n0 + r)*Dd + kc*64 + c8*8);
    }
    asm volatile("cp.async.commit_group;" ::: "memory");
}

__global__ __launch_bounds__(256, 2) void gemm_k(
    int mode,                       // 0 = QKV, 1 = OUT
    const float* __restrict__ b0, const float* __restrict__ b1, const float* __restrict__ b2,
    const float* __restrict__ mask, const float* __restrict__ xres, float* __restrict__ outp)
{
    extern __shared__ __half smh[];
    uint32_t smb = smem_u32(smh);
    int tid = threadIdx.x;
    int lane = tid & 31, w = tid >> 5;
    int g = lane >> 2, cq = lane & 3;
    int wm = w >> 1, wn = w & 1;
    int mBase = wm*32, nBase = wn*64;
    int m0 = blockIdx.y * 128;
    int n0 = blockIdx.x * 128;

    const __half* Ag = mode ? g_hs : g_xn;
    const __half* Bg = mode ? g_outT : g_qkvT;

    uint32_t aoff[2], boff[4];
    {
        int ar = lane & 15;
        int ac = (lane >> 4) * 8;
        #pragma unroll
        for (int mt = 0; mt < 2; mt++)
            aoff[mt] = (uint32_t)(((mBase + mt*16 + ar)*AROW + ac) * 2);
        int br = ((lane >> 4) << 3) | (lane & 7);
        int bc = ((lane >> 3) & 1) * 8;
        #pragma unroll
        for (int p = 0; p < 4; p++)
            boff[p] = (uint32_t)(((nBase + p*16 + br)*AROW + bc) * 2 + STG_A*2);
    }

    float acc[2][8][4];
    #pragma unroll
    for (int i = 0; i < 2; i++)
        #pragma unroll
        for (int j = 0; j < 8; j++)
            #pragma unroll
            for (int r = 0; r < 4; r++) acc[i][j][r] = 0.f;

    copy_stage(smh, 0, 0, Ag, Bg, m0, n0, tid);
    copy_stage(smh, 1, 1, Ag, Bg, m0, n0, tid);

    const int NIT = Dd/64;
    for (int it = 0; it < NIT; it++) {
        if (it + 2 < NIT) copy_stage(smh, (it+2)%3, it+2, Ag, Bg, m0, n0, tid);
        if (it + 2 < NIT)      asm volatile("cp.async.wait_group 2;" ::: "memory");
        else if (it + 1 < NIT) asm volatile("cp.async.wait_group 1;" ::: "memory");
        else                   asm volatile("cp.async.wait_group 0;" ::: "memory");
        __syncthreads();

        uint32_t stageB = smb + (uint32_t)((it%3)*STAGE_H*2);
        #pragma unroll
        for (int k16 = 0; k16 < 4; k16++) {
            uint32_t kb = (uint32_t)(k16*32);
            uint32_t a[2][4], bb[4][4];
            #pragma unroll
            for (int mt = 0; mt < 2; mt++) ldsm4(a[mt], stageB + aoff[mt] + kb);
            #pragma unroll
            for (int p = 0; p < 4; p++)    ldsm4(bb[p], stageB + boff[p] + kb);
            #pragma unroll
            for (int mt = 0; mt < 2; mt++)
                #pragma unroll
                for (int p = 0; p < 4; p++) {
                    mma_f16(acc[mt][2*p],   a[mt], &bb[p][0]);
                    mma_f16(acc[mt][2*p+1], a[mt], &bb[p][2]);
                }
        }
        __syncthreads();
    }

    // ---------------- register epilogue ----------------
    int region = n0 >> 9;
    const float* bia = (mode == 1) ? b0 : (region == 0 ? b0 : (region == 1 ? b1 : b2));
    int cbase = ((mode == 1) ? n0 : (n0 & 511)) + nBase + cq*2;
    float blo[8], bhi[8];
    #pragma unroll
    for (int nt = 0; nt < 8; nt++) { blo[nt] = bia[cbase + nt*8]; bhi[nt] = bia[cbase + nt*8 + 1]; }

    if (mode == 1) {
        #pragma unroll
        for (int mt = 0; mt < 2; mt++)
            #pragma unroll
            for (int rh = 0; rh < 2; rh++) {
                int m = m0 + mBase + mt*16 + g + rh*8;
                #pragma unroll
                for (int nt = 0; nt < 8; nt++) {
                    size_t off = (size_t)m*Dd + n0 + nBase + nt*8 + cq*2;
                    float2 xr = *(const float2*)(xres + off);
                    float2 o = make_float2(acc[mt][nt][2*rh]   + blo[nt] + xr.x,
                                           acc[mt][nt][2*rh+1] + bhi[nt] + xr.y);
                    *(float2*)(outp + off) = o;
                }
            }
    } else if (region == 0) {
        #pragma unroll
        for (int mt = 0; mt < 2; mt++)
            #pragma unroll
            for (int rh = 0; rh < 2; rh++) {
                int m = m0 + mBase + mt*16 + g + rh*8;
                float v0[8], v1[8];
                float mx = -1e30f;
                #pragma unroll
                for (int nt = 0; nt < 8; nt++) {
                    v0[nt] = acc[mt][nt][2*rh]   + blo[nt];
                    v1[nt] = acc[mt][nt][2*rh+1] + bhi[nt];
                    mx = fmaxf(mx, fmaxf(v0[nt], v1[nt]));
                }
                mx = fmaxf(mx, __shfl_xor_sync(0xffffffffu, mx, 1));
                mx = fmaxf(mx, __shfl_xor_sync(0xffffffffu, mx, 2));
                float s = 0.f;
                #pragma unroll
                for (int nt = 0; nt < 8; nt++) {
                    v0[nt] = __expf(v0[nt] - mx); v1[nt] = __expf(v1[nt] - mx);
                    s += v0[nt] + v1[nt];
                }
                s += __shfl_xor_sync(0xffffffffu, s, 1);
                s += __shfl_xor_sync(0xffffffffu, s, 2);
                float inv = 1.f / s;
                #pragma unroll
                for (int nt = 0; nt < 8; nt++)
                    *(__half2*)(g_qs + (size_t)m*Dd + cbase + nt*8) =
                        __floats2half2_rn(v0[nt]*inv, v1[nt]*inv);
            }
    } else if (region == 1) {
        float cs0[8] = {}, cs1[8] = {};
        #pragma unroll
        for (int mt = 0; mt < 2; mt++)
            #pragma unroll
            for (int rh = 0; rh < 2; rh++) {
                int m = m0 + mBase + mt*16 + g + rh*8;
                float madd = (1.f - mask[m]) * (-1e6f);
                #pragma unroll
                for (int nt = 0; nt < 8; nt++) {
                    float e0 = __expf(acc[mt][nt][2*rh]   + blo[nt] + madd);
                    float e1 = __expf(acc[mt][nt][2*rh+1] + bhi[nt] + madd);
                    __half2 h2 = __floats2half2_rn(e0, e1);
                    *(__half2*)(g_ek + (size_t)m*Dd + cbase + nt*8) = h2;
                    float2 hf = __half22float2(h2);
                    cs0[nt] += hf.x; cs1[nt] += hf.y;
                }
            }
        #pragma unroll
        for (int o = 4; o <= 16; o <<= 1)
            #pragma unroll
            for (int nt = 0; nt < 8; nt++) {
                cs0[nt] += __shfl_xor_sync(0xffffffffu, cs0[nt], o);
                cs1[nt] += __shfl_xor_sync(0xffffffffu, cs1[nt], o);
            }
        if (lane < 4) {
            int batch = m0 >> 13;
            #pragma unroll
            for (int nt = 0; nt < 8; nt++) {
                atomicAdd(&g_ksum[batch*Dd + cbase + nt*8],     cs0[nt]);
                atomicAdd(&g_ksum[batch*Dd + cbase + nt*8 + 1], cs1[nt]);
            }
        }
    } else {
        #pragma unroll
        for (int mt = 0; mt < 2; mt++)
            #pragma unroll
            for (int rh = 0; rh < 2; rh++) {
                int m = m0 + mBase + mt*16 + g + rh*8;
                float mv = mask[m];
                #pragma unroll
                for (int nt = 0; nt < 8; nt++)
                    *(__half2*)(g_vv + (size_t)m*Dd + cbase + nt*8) =
                        __floats2half2_rn((acc[mt][nt][2*rh]   + blo[nt])*mv,
                                          (acc[mt][nt][2*rh+1] + bhi[nt])*mv);
            }
    }
}

// ---------------- KV state (tf32 tensor, fp16 inputs); 256-token chunks ------
__global__ __launch_bounds__(128) void kv_k() {
    __shared__ float Es[64][72];
    __shared__ float Vs[64][72];
    int bh = blockIdx.x; int b = bh >> 3; int h = bh & 7;
    int t0 = b*Tt + blockIdx.y * 256;
    int tid = threadIdx.x;
    int lane = tid & 31, w = tid >> 5;
    int g = lane >> 2, cq = lane & 3;
    int mBase = w * 16;

    float acc[8][4];
    #pragma unroll
    for (int i = 0; i < 8; i++)
        #pragma unroll
        for (int r = 0; r < 4; r++) acc[i][r] = 0.f;

    for (int tile = 0; tile < 4; tile++) {
        #pragma unroll
        for (int i = 0; i < 8; i++) {
            int s = tid + i*128;
            int r = s >> 4, c4 = s & 15;
            size_t base = (size_t)(t0 + tile*64 + r)*Dd + h*DH + c4*4;
            const __half2* pe = (const __half2*)(g_ek + base);
            const __half2* pv = (const __half2*)(g_vv + base);
            float2 e0 = __half22float2(pe[0]), e1 = __half22float2(pe[1]);
            float2 v0 = __half22float2(pv[0]), v1 = __half22float2(pv[1]);
            *(float4*)&Es[r][c4*4] = make_float4(e0.x, e0.y, e1.x, e1.y);
            *(float4*)&Vs[r][c4*4] = make_float4(v0.x, v0.y, v1.x, v1.y);
        }
        __syncthreads();
        #pragma unroll
        for (int k8 = 0; k8 < 8; k8++) {
            int kk = k8*8;
            uint32_t a[4], bfr[8][2];
            a[0] = __float_as_uint(Es[kk+cq][mBase+g]);
            a[1] = __float_as_uint(Es[kk+cq][mBase+g+8]);
            a[2] = __float_as_uint(Es[kk+cq+4][mBase+g]);
            a[3] = __float_as_uint(Es[kk+cq+4][mBase+g+8]);
            #pragma unroll
            for (int nt = 0; nt < 8; nt++) {
                bfr[nt][0] = __float_as_uint(Vs[kk+cq][nt*8+g]);
                bfr[nt][1] = __float_as_uint(Vs[kk+cq+4][nt*8+g]);
            }
            #pragma unroll
            for (int nt = 0; nt < 8; nt++)
                mma_tf32(acc[nt], a, bfr[nt]);
        }
        __syncthreads();
    }
    float* A = g_attn + (size_t)bh*DH*DH;
    #pragma unroll
    for (int nt = 0; nt < 8; nt++) {
        int n = nt*8 + cq*2;
        atomicAdd(&A[(mBase+g)*DH + n],     acc[nt][0]);
        atomicAdd(&A[(mBase+g)*DH + n+1],   acc[nt][1]);
        atomicAdd(&A[(mBase+g+8)*DH + n],   acc[nt][2]);
        atomicAdd(&A[(mBase+g+8)*DH + n+1], acc[nt][3]);
    }
}

// ---------------- y = q_h @ (attn_h / ksum) (tf32 tensor, fp16 in/out) --------
__global__ __launch_bounds__(128) void y_k() {
    __shared__ float Qs[64][68];
    __shared__ float Ahs[64][72];
    int bh = blockIdx.x; int b = bh >> 3; int h = bh & 7;
    int t0 = b*Tt + blockIdx.y * 64;
    int tid = threadIdx.x;
    int lane = tid & 31, w = tid >> 5;
    int g = lane >> 2, cq = lane & 3;
    int mBase = w * 16;

    {
        const float* A  = g_attn + (size_t)bh*DH*DH;
        const float* ks = g_ksum + b*Dd + h*DH;
        #pragma unroll
        for (int i = 0; i < 8; i++) {
            int s = tid + i*128;
            int r = s >> 4, c4 = s & 15;
            float rk = 1.f / ks[r];
            float4 a = *(const float4*)(A + r*DH + c4*4);
            a.x *= rk; a.y *= rk; a.z *= rk; a.w *= rk;
            *(float4*)&Ahs[r][c4*4] = a;
            const __half2* pq = (const __half2*)(g_qs + (size_t)(t0 + r)*Dd + h*DH + c4*4);
            float2 q0 = __half22float2(pq[0]), q1 = __half22float2(pq[1]);
            *(float4*)&Qs[r][c4*4] = make_float4(q0.x, q0.y, q1.x, q1.y);
        }
    }
    __syncthreads();

    float acc[8][4];
    #pragma unroll
    for (int i = 0; i < 8; i++)
        #pragma unroll
        for (int r = 0; r < 4; r++) acc[i][r] = 0.f;

    #pragma unroll
    for (int k8 = 0; k8 < 8; k8++) {
        int kk = k8*8;
        uint32_t a[4], bfr[8][2];
        a[0] = __float_as_uint(Qs[mBase+g][kk+cq]);
        a[1] = __float_as_uint(Qs[mBase+g+8][kk+cq]);
        a[2] = __float_as_uint(Qs[mBase+g][kk+cq+4]);
        a[3] = __float_as_uint(Qs[mBase+g+8][kk+cq+4]);
        #pragma unroll
        for (int nt = 0; nt < 8; nt++) {
            bfr[nt][0] = __float_as_uint(Ahs[kk+cq][nt*8+g]);
            bfr[nt][1] = __float_as_uint(Ahs[kk+cq+4][nt*8+g]);
        }
        #pragma unroll
        for (int nt = 0; nt < 8; nt++)
            mma_tf32(acc[nt], a, bfr[nt]);
    }

    #pragma unroll
    for (int nt = 0; nt < 8; nt++) {
        int n = h*DH + nt*8 + cq*2;
        size_t r0 = (size_t)(t0 + mBase + g)*Dd + n;
        size_t r1 = (size_t)(t0 + mBase + g + 8)*Dd + n;
        *(__half2*)(g_y + r0) = __floats2half2_rn(acc[nt][0], acc[nt][1]);
        *(__half2*)(g_y + r1) = __floats2half2_rn(acc[nt][2], acc[nt][3]);
    }
}

// ---------------- stylize + silu -> g_hs (fp16 in/out) ----------------
__global__ void style_k(const float* __restrict__ g2, const float* __restrict__ b2) {
    int tok = blockIdx.x, tid = threadIdx.x;
    int b = tok >> 13;
    const __half2* py = (const __half2*)(g_y + (size_t)tok*Dd);
    float2 y01 = __half22float2(py[tid*2]);
    float2 y23 = __half22float2(py[tid*2+1]);
    float s = y01.x + y01.y + y23.x + y23.y;
    __shared__ float r1[4], r2[4];
    for (int o = 16; o; o >>= 1) s += __shfl_xor_sync(0xffffffffu, s, o);
    if ((tid & 31) == 0) r1[tid >> 5] = s;
    __syncthreads();
    float mu = (r1[0] + r1[1] + r1[2] + r1[3]) * (1.f / Dd);
    float a = y01.x - mu, bb_ = y01.y - mu, c = y23.x - mu, d = y23.y - mu;
    float ss = a*a + bb_*bb_ + c*c + d*d;
    for (int o = 16; o; o >>= 1) ss += __shfl_xor_sync(0xffffffffu, ss, o);
    if ((tid & 31) == 0) r2[tid >> 5] = ss;
    __syncthreads();
    float var = (r2[0] + r2[1] + r2[2] + r2[3]) * (1.f / Dd);
    float rs = rsqrtf(var + 1e-5f);
    float4 gg = ((const float4*)g2)[tid], bt = ((const float4*)b2)[tid];
    float4 sc = ((const float4*)(g_emb + b*2*Dd))[tid];
    float4 sh = ((const float4*)(g_emb + b*2*Dd + Dd))[tid];
    float h0 = (a  *rs*gg.x + bt.x)*(1.f + sc.x) + sh.x;
    float h1 = (bb_*rs*gg.y + bt.y)*(1.f + sc.y) + sh.y;
    float h2 = (c  *rs*gg.z + bt.z)*(1.f + sc.z) + sh.z;
    float h3 = (d  *rs*gg.w + bt.w)*(1.f + sc.w) + sh.w;
    h0 = h0 / (1.f + __expf(-h0));
    h1 = h1 / (1.f + __expf(-h1));
    h2 = h2 / (1.f + __expf(-h2));
    h3 = h3 / (1.f + __expf(-h3));
    __half2* ph = (__half2*)(g_hs + (size_t)tok*Dd);
    ph[tid*2]   = __halves2half2(__float2half_rn(h0), __float2half_rn(h1));
    ph[tid*2+1] = __halves2half2(__float2half_rn(h2), __float2half_rn(h3));
}

// ---------------- launch ----------------
extern "C" void kernel_launch(void* const* d_in, const int* in_sizes, int n_in,
                              void* d_out, int out_size) {
    const float* x     = (const float*)d_in[0];
    const float* emb   = (const float*)d_in[1];
    const float* mask  = (const float*)d_in[2];
    const float* gamma = (const float*)d_in[3];
    const float* beta  = (const float*)d_in[4];
    const float* Wq    = (const float*)d_in[5];
    const float* bq    = (const float*)d_in[6];
    const float* Wk    = (const float*)d_in[7];
    const float* bk    = (const float*)d_in[8];
    const float* Wv    = (const float*)d_in[9];
    const float* bv    = (const float*)d_in[10];
    const float* embW  = (const float*)d_in[11];
    const float* embB  = (const float*)d_in[12];
    const float* g2    = (const float*)d_in[13];
    const float* b2    = (const float*)d_in[14];
    const float* outW  = (const float*)d_in[15];
    const float* outB  = (const float*)d_in[16];
    float* out = (float*)d_out;

    static int inited = 0;
    static cudaStream_t s2;
    static cudaEvent_t ev0, ev1;
    if (!inited) {
        cudaFuncSetAttribute(gemm_k, cudaFuncAttributeMaxDynamicSharedMemorySize, SMEM_BYTES);
        cudaStreamCreateWithFlags(&s2, cudaStreamNonBlocking);
        cudaEventCreateWithFlags(&ev0, cudaEventDisableTiming);
        cudaEventCreateWithFlags(&ev1, cudaEventDisableTiming);
        inited = 1;
    }

    // fork: {wconv, emb} on s2 || {ln} on main; join before QKV GEMM
    zero_k <<<512, 256>>>(embB);
    cudaEventRecord(ev0, 0);
    cudaStreamWaitEvent(s2, ev0, 0);
    wconv_k<<<dim3(16, 16, 4), dim3(32, 8), 0, s2>>>(Wq, Wk, Wv, outW);
    emb_k  <<<dim3(Bb, 8, 8), 256, 0, s2>>>(emb, embW);
    cudaEventRecord(ev1, s2);
    ln_k   <<<NTOK, 128>>>(x, gamma, beta);
    cudaStreamWaitEvent(0, ev1, 0);

    gemm_k <<<dim3(12, NTOK/128), 256, SMEM_BYTES>>>(0, bq, bk, bv, mask, nullptr, nullptr);
    kv_k   <<<dim3(Bb*Hh, 32), 128>>>();
    y_k    <<<dim3(Bb*Hh, Tt/64), 128>>>();
    style_k<<<NTOK, 128>>>(g2, b2);
    gemm_k <<<dim3(4, NTOK/128), 256, SMEM_BYTES>>>(1, outB, nullptr, nullptr, nullptr, x, out);
}

// round 16
// speedup vs baseline: 1.0851x; 1.0439x over previous
#include <cuda_runtime.h>
#include <cuda_fp16.h>
#include <math.h>
#include <stdint.h>

#define Bb   4
#define Tt   8192
#define Dd   512
#define Hh   8
#define DH   64
#define TEE  2048
#define NTOK (Bb*Tt)

// ---------------- scratch ----------------
__device__ __half g_xn[NTOK*Dd];           // LN(x), fp16
__device__ __half g_hs[NTOK*Dd];           // silu(stylized), fp16
__device__ __half g_qkvT[3*Dd*Dd];         // [1536][512] W^T fp16
__device__ __half g_outT[Dd*Dd];           // [512][512]  W^T fp16
__device__ __half g_qs[NTOK*Dd];           // softmaxed q, fp16
__device__ __half g_ek[NTOK*Dd];           // exp(k), fp16
__device__ __half g_vv[NTOK*Dd];           // masked v, fp16
__device__ __half g_y [NTOK*Dd];           // attention out, fp16
__device__ float g_ksum[Bb*Dd];
__device__ float g_attn[Bb*Hh*DH*DH];
__device__ float g_emb[Bb*2*Dd];

// ---------------- helpers ----------------
__device__ __forceinline__ uint32_t smem_u32(const void* p) {
    uint32_t a;
    asm("{ .reg .u64 t; cvta.to.shared.u64 t, %1; cvt.u32.u64 %0, t; }" : "=r"(a) : "l"(p));
    return a;
}
__device__ __forceinline__ void cp16(void* dst, const void* src) {
    uint32_t d;
    asm("{ .reg .u64 t; cvta.to.shared.u64 t, %1; cvt.u32.u64 %0, t; }" : "=r"(d) : "l"(dst));
    asm volatile("cp.async.cg.shared.global [%0], [%1], 16;" :: "r"(d), "l"(src) : "memory");
}
__device__ __forceinline__ void ldsm4(uint32_t* r, uint32_t addr) {
    asm volatile("ldmatrix.sync.aligned.m8n8.x4.shared.b16 {%0,%1,%2,%3}, [%4];"
        : "=r"(r[0]), "=r"(r[1]), "=r"(r[2]), "=r"(r[3]) : "r"(addr));
}
__device__ __forceinline__ void mma_f16(float* c, const uint32_t* a, const uint32_t* b) {
    asm volatile(
        "mma.sync.aligned.m16n8k16.row.col.f32.f16.f16.f32 "
        "{%0,%1,%2,%3}, {%4,%5,%6,%7}, {%8,%9}, {%0,%1,%2,%3};"
        : "+f"(c[0]), "+f"(c[1]), "+f"(c[2]), "+f"(c[3])
        : "r"(a[0]), "r"(a[1]), "r"(a[2]), "r"(a[3]), "r"(b[0]), "r"(b[1]));
}
__device__ __forceinline__ void mma_tf32(float* c, const uint32_t* a, const uint32_t* b) {
    asm volatile(
        "mma.sync.aligned.m16n8k8.row.col.f32.tf32.tf32.f32 "
        "{%0,%1,%2,%3}, {%4,%5,%6,%7}, {%8,%9}, {%0,%1,%2,%3};"
        : "+f"(c[0]), "+f"(c[1]), "+f"(c[2]), "+f"(c[3])
        : "r"(a[0]), "r"(a[1]), "r"(a[2]), "r"(a[3]), "r"(b[0]), "r"(b[1]));
}

// ---------------- zero accumulators + seed emb with bias ----------------
__global__ void zero_k(const float* __restrict__ embB) {
    int i = blockIdx.x * blockDim.x + threadIdx.x;
    if (i < Bb*Dd) g_ksum[i] = 0.f;
    if (i < Bb*Hh*DH*DH) g_attn[i] = 0.f;
    if (i < Bb*2*Dd) g_emb[i] = embB[i & (2*Dd - 1)];
}

// ---------------- weight transpose + fp16 ----------------
__global__ void wconv_k(const float* __restrict__ Wq, const float* __restrict__ Wk,
                        const float* __restrict__ Wv, const float* __restrict__ Wo) {
    __shared__ float t[32][33];
    int mat = blockIdx.z;
    const float* W = mat == 0 ? Wq : mat == 1 ? Wk : mat == 2 ? Wv : Wo;
    int k0 = blockIdx.y * 32, n0 = blockIdx.x * 32;
    int tx = threadIdx.x, ty = threadIdx.y;
    #pragma unroll
    for (int i = 0; i < 4; i++)
        t[ty + i*8][tx] = W[(size_t)(k0 + ty + i*8)*Dd + n0 + tx];
    __syncthreads();
    __half* dst = (mat < 3) ? g_qkvT : g_outT;
    int nbase = (mat < 3) ? mat*Dd : 0;
    #pragma unroll
    for (int i = 0; i < 4; i++) {
        int n = n0 + ty + i*8, k = k0 + tx;
        dst[(size_t)(nbase + n)*Dd + k] = __float2half_rn(t[tx][ty + i*8]);
    }
}

// ---------------- emb partial: silu(emb_chunk) @ W_chunk, atomic add ----------
__global__ void emb_k(const float* __restrict__ emb,
                      const float* __restrict__ W) {
    __shared__ float se[256];
    int b = blockIdx.x, oc = blockIdx.y, ec = blockIdx.z;
    int tid = threadIdx.x;
    if (tid < 128) {
        #pragma unroll
        for (int i = 0; i < 2; i++) {
            float e = emb[b*TEE + ec*256 + tid*2 + i];
            se[tid*2 + i] = e / (1.f + __expf(-e));
        }
    }
    __syncthreads();
    int o = oc*128 + (tid & 127);
    int eh = (tid >> 7) * 128;
    float acc = 0.f;
    #pragma unroll 4
    for (int e = 0; e < 128; e++)
        acc += se[eh + e] * W[(size_t)(ec*256 + eh + e)*(2*Dd) + o];
    atomicAdd(&g_emb[b*2*Dd + o], acc);
}

// ---------------- LN(x) -> g_xn (fp16) ----------------
__global__ void ln_k(const float* __restrict__ x,
                     const float* __restrict__ g,
                     const float* __restrict__ be) {
    int tok = blockIdx.x, tid = threadIdx.x;
    float4 v = ((const float4*)(x + (size_t)tok*Dd))[tid];
    float s = v.x + v.y + v.z + v.w;
    __shared__ float r1[4], r2[4];
    for (int o = 16; o; o >>= 1) s += __shfl_xor_sync(0xffffffffu, s, o);
    if ((tid & 31) == 0) r1[tid >> 5] = s;
    __syncthreads();
    float mu = (r1[0] + r1[1] + r1[2] + r1[3]) * (1.f / Dd);
    float a = v.x - mu, b = v.y - mu, c = v.z - mu, d = v.w - mu;
    float ss = a*a + b*b + c*c + d*d;
    for (int o = 16; o; o >>= 1) ss += __shfl_xor_sync(0xffffffffu, ss, o);
    if ((tid & 31) == 0) r2[tid >> 5] = ss;
    __syncthreads();
    float var = (r2[0] + r2[1] + r2[2] + r2[3]) * (1.f / Dd);
    float rs = rsqrtf(var + 1e-5f);
    float4 gg = ((const float4*)g)[tid], bb = ((const float4*)be)[tid];
    __half2* ph = (__half2*)(g_xn + (size_t)tok*Dd);
    ph[tid*2]   = __halves2half2(__float2half_rn(a*rs*gg.x + bb.x),
                                 __float2half_rn(b*rs*gg.y + bb.y));
    ph[tid*2+1] = __halves2half2(__float2half_rn(c*rs*gg.z + bb.z),
                                 __float2half_rn(d*rs*gg.w + bb.w));
}

// ---------------- fp16 HMMA GEMM: BM=128, BN=128, BK=64, single-sync loop ----
#define AROW 72
#define STG_A (128*AROW)
#define STG_B (128*AROW)
#define STAGE_H (STG_A + STG_B)
#define SMEM_BYTES (3*STAGE_H*2)           // 110592 B -> 2 CTAs/SM

__device__ __forceinline__ void copy_stage(__half* smh, int st, int kc,
    const __half* __restrict__ Ag, const __half* __restrict__ Bg,
    int m0, int n0, int tid)
{
    __half* A = smh + st*STAGE_H;
    __half* B = A + STG_A;
    #pragma unroll
    for (int i = 0; i < 4; i++) {
        int s = tid + i*256;
        int r = s >> 3, c8 = s & 7;
        cp16(A + r*AROW + c8*8, Ag + (size_t)(m0 + r)*Dd + kc*64 + c8*8);
    }
    #pragma unroll
    for (int i = 0; i < 4; i++) {
        int s = tid + i*256;
        int r = s >> 3, c8 = s & 7;
        cp16(B + r*AROW + c8*8, Bg + (size_t)(n0 + r)*Dd + kc*64 + c8*8);
    }
    asm volatile("cp.async.commit_group;" ::: "memory");
}

__global__ __launch_bounds__(256, 2) void gemm_k(
    int mode,                       // 0 = QKV, 1 = OUT
    const float* __restrict__ b0, const float* __restrict__ b1, const float* __restrict__ b2,
    const float* __restrict__ mask, const float* __restrict__ xres, float* __restrict__ outp)
{
    extern __shared__ __half smh[];
    uint32_t smb = smem_u32(smh);
    int tid = threadIdx.x;
    int lane = tid & 31, w = tid >> 5;
    int g = lane >> 2, cq = lane & 3;
    int wm = w >> 1, wn = w & 1;
    int mBase = wm*32, nBase = wn*64;
    int m0 = blockIdx.y * 128;
    int n0 = blockIdx.x * 128;

    const __half* Ag = mode ? g_hs : g_xn;
    const __half* Bg = mode ? g_outT : g_qkvT;

    uint32_t aoff[2], boff[4];
    {
        int ar = lane & 15;
        int ac = (lane >> 4) * 8;
        #pragma unroll
        for (int mt = 0; mt < 2; mt++)
            aoff[mt] = (uint32_t)(((mBase + mt*16 + ar)*AROW + ac) * 2);
        int br = ((lane >> 4) << 3) | (lane & 7);
        int bc = ((lane >> 3) & 1) * 8;
        #pragma unroll
        for (int p = 0; p < 4; p++)
            boff[p] = (uint32_t)(((nBase + p*16 + br)*AROW + bc) * 2 + STG_A*2);
    }

    float acc[2][8][4];
    #pragma unroll
    for (int i = 0; i < 2; i++)
        #pragma unroll
        for (int j = 0; j < 8; j++)
            #pragma unroll
            for (int r = 0; r < 4; r++) acc[i][j][r] = 0.f;

    copy_stage(smh, 0, 0, Ag, Bg, m0, n0, tid);
    copy_stage(smh, 1, 1, Ag, Bg, m0, n0, tid);

    // single-sync mainloop: wait -> sync -> MMA(it) -> issue copy(it+2)
    const int NIT = Dd/64;                 // 8
    for (int it = 0; it < NIT; it++) {
        if (it + 1 < NIT) asm volatile("cp.async.wait_group 1;" ::: "memory");
        else              asm volatile("cp.async.wait_group 0;" ::: "memory");
        __syncthreads();

        uint32_t stageB = smb + (uint32_t)((it%3)*STAGE_H*2);
        #pragma unroll
        for (int k16 = 0; k16 < 4; k16++) {
            uint32_t kb = (uint32_t)(k16*32);
            uint32_t a[2][4], bb[4][4];
            #pragma unroll
            for (int mt = 0; mt < 2; mt++) ldsm4(a[mt], stageB + aoff[mt] + kb);
            #pragma unroll
            for (int p = 0; p < 4; p++)    ldsm4(bb[p], stageB + boff[p] + kb);
            #pragma unroll
            for (int mt = 0; mt < 2; mt++)
                #pragma unroll
                for (int p = 0; p < 4; p++) {
                    mma_f16(acc[mt][2*p],   a[mt], &bb[p][0]);
                    mma_f16(acc[mt][2*p+1], a[mt], &bb[p][2]);
                }
        }
        if (it + 2 < NIT) copy_stage(smh, (it+2)%3, it+2, Ag, Bg, m0, n0, tid);
    }

    // ---------------- register epilogue ----------------
    int region = n0 >> 9;
    const float* bia = (mode == 1) ? b0 : (region == 0 ? b0 : (region == 1 ? b1 : b2));
    int cbase = ((mode == 1) ? n0 : (n0 & 511)) + nBase + cq*2;
    float blo[8], bhi[8];
    #pragma unroll
    for (int nt = 0; nt < 8; nt++) { blo[nt] = bia[cbase + nt*8]; bhi[nt] = bia[cbase + nt*8 + 1]; }

    if (mode == 1) {
        #pragma unroll
        for (int mt = 0; mt < 2; mt++)
            #pragma unroll
            for (int rh = 0; rh < 2; rh++) {
                int m = m0 + mBase + mt*16 + g + rh*8;
                #pragma unroll
                for (int nt = 0; nt < 8; nt++) {
                    size_t off = (size_t)m*Dd + n0 + nBase + nt*8 + cq*2;
                    float2 xr = *(const float2*)(xres + off);
                    float2 o = make_float2(acc[mt][nt][2*rh]   + blo[nt] + xr.x,
                                           acc[mt][nt][2*rh+1] + bhi[nt] + xr.y);
                    *(float2*)(outp + off) = o;
                }
            }
    } else if (region == 0) {
        #pragma unroll
        for (int mt = 0; mt < 2; mt++)
            #pragma unroll
            for (int rh = 0; rh < 2; rh++) {
                int m = m0 + mBase + mt*16 + g + rh*8;
                float v0[8], v1[8];
                float mx = -1e30f;
                #pragma unroll
                for (int nt = 0; nt < 8; nt++) {
                    v0[nt] = acc[mt][nt][2*rh]   + blo[nt];
                    v1[nt] = acc[mt][nt][2*rh+1] + bhi[nt];
                    mx = fmaxf(mx, fmaxf(v0[nt], v1[nt]));
                }
                mx = fmaxf(mx, __shfl_xor_sync(0xffffffffu, mx, 1));
                mx = fmaxf(mx, __shfl_xor_sync(0xffffffffu, mx, 2));
                float s = 0.f;
                #pragma unroll
                for (int nt = 0; nt < 8; nt++) {
                    v0[nt] = __expf(v0[nt] - mx); v1[nt] = __expf(v1[nt] - mx);
                    s += v0[nt] + v1[nt];
                }
                s += __shfl_xor_sync(0xffffffffu, s, 1);
                s += __shfl_xor_sync(0xffffffffu, s, 2);
                float inv = 1.f / s;
                #pragma unroll
                for (int nt = 0; nt < 8; nt++)
                    *(__half2*)(g_qs + (size_t)m*Dd + cbase + nt*8) =
                        __floats2half2_rn(v0[nt]*inv, v1[nt]*inv);
            }
    } else if (region == 1) {
        float cs0[8] = {}, cs1[8] = {};
        #pragma unroll
        for (int mt = 0; mt < 2; mt++)
            #pragma unroll
            for (int rh = 0; rh < 2; rh++) {
                int m = m0 + mBase + mt*16 + g + rh*8;
                float madd = (1.f - mask[m]) * (-1e6f);
                #pragma unroll
                for (int nt = 0; nt < 8; nt++) {
                    float e0 = __expf(acc[mt][nt][2*rh]   + blo[nt] + madd);
                    float e1 = __expf(acc[mt][nt][2*rh+1] + bhi[nt] + madd);
                    __half2 h2 = __floats2half2_rn(e0, e1);
                    *(__half2*)(g_ek + (size_t)m*Dd + cbase + nt*8) = h2;
                    float2 hf = __half22float2(h2);
                    cs0[nt] += hf.x; cs1[nt] += hf.y;
                }
            }
        #pragma unroll
        for (int o = 4; o <= 16; o <<= 1)
            #pragma unroll
            for (int nt = 0; nt < 8; nt++) {
                cs0[nt] += __shfl_xor_sync(0xffffffffu, cs0[nt], o);
                cs1[nt] += __shfl_xor_sync(0xffffffffu, cs1[nt], o);
            }
        if (lane < 4) {
            int batch = m0 >> 13;
            #pragma unroll
            for (int nt = 0; nt < 8; nt++) {
                atomicAdd(&g_ksum[batch*Dd + cbase + nt*8],     cs0[nt]);
                atomicAdd(&g_ksum[batch*Dd + cbase + nt*8 + 1], cs1[nt]);
            }
        }
    } else {
        #pragma unroll
        for (int mt = 0; mt < 2; mt++)
            #pragma unroll
            for (int rh = 0; rh < 2; rh++) {
                int m = m0 + mBase + mt*16 + g + rh*8;
                float mv = mask[m];
                #pragma unroll
                for (int nt = 0; nt < 8; nt++)
                    *(__half2*)(g_vv + (size_t)m*Dd + cbase + nt*8) =
                        __floats2half2_rn((acc[mt][nt][2*rh]   + blo[nt])*mv,
                                          (acc[mt][nt][2*rh+1] + bhi[nt])*mv);
            }
    }
}

// ---------------- KV state (tf32 tensor, fp16 inputs) ----------------
__global__ __launch_bounds__(128) void kv_k() {
    __shared__ float Es[64][72];
    __shared__ float Vs[64][72];
    int bh = blockIdx.x; int b = bh >> 3; int h = bh & 7;
    int t0 = b*Tt + blockIdx.y * 512;
    int tid = threadIdx.x;
    int lane = tid & 31, w = tid >> 5;
    int g = lane >> 2, cq = lane & 3;
    int mBase = w * 16;

    float acc[8][4];
    #pragma unroll
    for (int i = 0; i < 8; i++)
        #pragma unroll
        for (int r = 0; r < 4; r++) acc[i][r] = 0.f;

    for (int tile = 0; tile < 8; tile++) {
        #pragma unroll
        for (int i = 0; i < 8; i++) {
            int s = tid + i*128;
            int r = s >> 4, c4 = s & 15;
            size_t base = (size_t)(t0 + tile*64 + r)*Dd + h*DH + c4*4;
            const __half2* pe = (const __half2*)(g_ek + base);
            const __half2* pv = (const __half2*)(g_vv + base);
            float2 e0 = __half22float2(pe[0]), e1 = __half22float2(pe[1]);
            float2 v0 = __half22float2(pv[0]), v1 = __half22float2(pv[1]);
            *(float4*)&Es[r][c4*4] = make_float4(e0.x, e0.y, e1.x, e1.y);
            *(float4*)&Vs[r][c4*4] = make_float4(v0.x, v0.y, v1.x, v1.y);
        }
        __syncthreads();
        #pragma unroll
        for (int k8 = 0; k8 < 8; k8++) {
            int kk = k8*8;
            uint32_t a[4], bfr[8][2];
            a[0] = __float_as_uint(Es[kk+cq][mBase+g]);
            a[1] = __float_as_uint(Es[kk+cq][mBase+g+8]);
            a[2] = __float_as_uint(Es[kk+cq+4][mBase+g]);
            a[3] = __float_as_uint(Es[kk+cq+4][mBase+g+8]);
            #pragma unroll
            for (int nt = 0; nt < 8; nt++) {
                bfr[nt][0] = __float_as_uint(Vs[kk+cq][nt*8+g]);
                bfr[nt][1] = __float_as_uint(Vs[kk+cq+4][nt*8+g]);
            }
            #pragma unroll
            for (int nt = 0; nt < 8; nt++)
                mma_tf32(acc[nt], a, bfr[nt]);
        }
        __syncthreads();
    }
    float* A = g_attn + (size_t)bh*DH*DH;
    #pragma unroll
    for (int nt = 0; nt < 8; nt++) {
        int n = nt*8 + cq*2;
        atomicAdd(&A[(mBase+g)*DH + n],     acc[nt][0]);
        atomicAdd(&A[(mBase+g)*DH + n+1],   acc[nt][1]);
        atomicAdd(&A[(mBase+g+8)*DH + n],   acc[nt][2]);
        atomicAdd(&A[(mBase+g+8)*DH + n+1], acc[nt][3]);
    }
}

// ---------------- y = q_h @ (attn_h / ksum) (tf32 tensor, fp16 in/out) --------
__global__ __launch_bounds__(128) void y_k() {
    __shared__ float Qs[64][68];
    __shared__ float Ahs[64][72];
    int bh = blockIdx.x; int b = bh >> 3; int h = bh & 7;
    int t0 = b*Tt + blockIdx.y * 64;
    int tid = threadIdx.x;
    int lane = tid & 31, w = tid >> 5;
    int g = lane >> 2, cq = lane & 3;
    int mBase = w * 16;

    {
        const float* A  = g_attn + (size_t)bh*DH*DH;
        const float* ks = g_ksum + b*Dd + h*DH;
        #pragma unroll
        for (int i = 0; i < 8; i++) {
            int s = tid + i*128;
            int r = s >> 4, c4 = s & 15;
            float rk = 1.f / ks[r];
            float4 a = *(const float4*)(A + r*DH + c4*4);
            a.x *= rk; a.y *= rk; a.z *= rk; a.w *= rk;
            *(float4*)&Ahs[r][c4*4] = a;
            const __half2* pq = (const __half2*)(g_qs + (size_t)(t0 + r)*Dd + h*DH + c4*4);
            float2 q0 = __half22float2(pq[0]), q1 = __half22float2(pq[1]);
            *(float4*)&Qs[r][c4*4] = make_float4(q0.x, q0.y, q1.x, q1.y);
        }
    }
    __syncthreads();

    float acc[8][4];
    #pragma unroll
    for (int i = 0; i < 8; i++)
        #pragma unroll
        for (int r = 0; r < 4; r++) acc[i][r] = 0.f;

    #pragma unroll
    for (int k8 = 0; k8 < 8; k8++) {
        int kk = k8*8;
        uint32_t a[4], bfr[8][2];
        a[0] = __float_as_uint(Qs[mBase+g][kk+cq]);
        a[1] = __float_as_uint(Qs[mBase+g+8][kk+cq]);
        a[2] = __float_as_uint(Qs[mBase+g][kk+cq+4]);
        a[3] = __float_as_uint(Qs[mBase+g+8][kk+cq+4]);
        #pragma unroll
        for (int nt = 0; nt < 8; nt++) {
            bfr[nt][0] = __float_as_uint(Ahs[kk+cq][nt*8+g]);
            bfr[nt][1] = __float_as_uint(Ahs[kk+cq+4][nt*8+g]);
        }
        #pragma unroll
        for (int nt = 0; nt < 8; nt++)
            mma_tf32(acc[nt], a, bfr[nt]);
    }

    #pragma unroll
    for (int nt = 0; nt < 8; nt++) {
        int n = h*DH + nt*8 + cq*2;
        size_t r0 = (size_t)(t0 + mBase + g)*Dd + n;
        size_t r1 = (size_t)(t0 + mBase + g + 8)*Dd + n;
        *(__half2*)(g_y + r0) = __floats2half2_rn(acc[nt][0], acc[nt][1]);
        *(__half2*)(g_y + r1) = __floats2half2_rn(acc[nt][2], acc[nt][3]);
    }
}

// ---------------- stylize + silu -> g_hs (fp16 in/out) ----------------
__global__ void style_k(const float* __restrict__ g2, const float* __restrict__ b2) {
    int tok = blockIdx.x, tid = threadIdx.x;
    int b = tok >> 13;
    const __half2* py = (const __half2*)(g_y + (size_t)tok*Dd);
    float2 y01 = __half22float2(py[tid*2]);
    float2 y23 = __half22float2(py[tid*2+1]);
    float s = y01.x + y01.y + y23.x + y23.y;
    __shared__ float r1[4], r2[4];
    for (int o = 16; o; o >>= 1) s += __shfl_xor_sync(0xffffffffu, s, o);
    if ((tid & 31) == 0) r1[tid >> 5] = s;
    __syncthreads();
    float mu = (r1[0] + r1[1] + r1[2] + r1[3]) * (1.f / Dd);
    float a = y01.x - mu, bb_ = y01.y - mu, c = y23.x - mu, d = y23.y - mu;
    float ss = a*a + bb_*bb_ + c*c + d*d;
    for (int o = 16; o; o >>= 1) ss += __shfl_xor_sync(0xffffffffu, ss, o);
    if ((tid & 31) == 0) r2[tid >> 5] = ss;
    __syncthreads();
    float var = (r2[0] + r2[1] + r2[2] + r2[3]) * (1.f / Dd);
    float rs = rsqrtf(var + 1e-5f);
    float4 gg = ((const float4*)g2)[tid], bt = ((const float4*)b2)[tid];
    float4 sc = ((const float4*)(g_emb + b*2*Dd))[tid];
    float4 sh = ((const float4*)(g_emb + b*2*Dd + Dd))[tid];
    float h0 = (a  *rs*gg.x + bt.x)*(1.f + sc.x) + sh.x;
    float h1 = (bb_*rs*gg.y + bt.y)*(1.f + sc.y) + sh.y;
    float h2 = (c  *rs*gg.z + bt.z)*(1.f + sc.z) + sh.z;
    float h3 = (d  *rs*gg.w + bt.w)*(1.f + sc.w) + sh.w;
    h0 = h0 / (1.f + __expf(-h0));
    h1 = h1 / (1.f + __expf(-h1));
    h2 = h2 / (1.f + __expf(-h2));
    h3 = h3 / (1.f + __expf(-h3));
    __half2* ph = (__half2*)(g_hs + (size_t)tok*Dd);
    ph[tid*2]   = __halves2half2(__float2half_rn(h0), __float2half_rn(h1));
    ph[tid*2+1] = __halves2half2(__float2half_rn(h2), __float2half_rn(h3));
}

// ---------------- launch ----------------
extern "C" void kernel_launch(void* const* d_in, const int* in_sizes, int n_in,
                              void* d_out, int out_size) {
    const float* x     = (const float*)d_in[0];
    const float* emb   = (const float*)d_in[1];
    const float* mask  = (const float*)d_in[2];
    const float* gamma = (const float*)d_in[3];
    const float* beta  = (const float*)d_in[4];
    const float* Wq    = (const float*)d_in[5];
    const float* bq    = (const float*)d_in[6];
    const float* Wk    = (const float*)d_in[7];
    const float* bk    = (const float*)d_in[8];
    const float* Wv    = (const float*)d_in[9];
    const float* bv    = (const float*)d_in[10];
    const float* embW  = (const float*)d_in[11];
    const float* embB  = (const float*)d_in[12];
    const float* g2    = (const float*)d_in[13];
    const float* b2    = (const float*)d_in[14];
    const float* outW  = (const float*)d_in[15];
    const float* outB  = (const float*)d_in[16];
    float* out = (float*)d_out;

    static int inited = 0;
    static cudaStream_t s2;
    static cudaEvent_t ev0, ev1;
    if (!inited) {
        cudaFuncSetAttribute(gemm_k, cudaFuncAttributeMaxDynamicSharedMemorySize, SMEM_BYTES);
        cudaStreamCreateWithFlags(&s2, cudaStreamNonBlocking);
        cudaEventCreateWithFlags(&ev0, cudaEventDisableTiming);
        cudaEventCreateWithFlags(&ev1, cudaEventDisableTiming);
        inited = 1;
    }

    // fork: {wconv, emb} on s2 || {ln} on main; join before QKV GEMM
    zero_k <<<512, 256>>>(embB);
    cudaEventRecord(ev0, 0);
    cudaStreamWaitEvent(s2, ev0, 0);
    wconv_k<<<dim3(16, 16, 4), dim3(32, 8), 0, s2>>>(Wq, Wk, Wv, outW);
    emb_k  <<<dim3(Bb, 8, 8), 256, 0, s2>>>(emb, embW);
    cudaEventRecord(ev1, s2);
    ln_k   <<<NTOK, 128>>>(x, gamma, beta);
    cudaStreamWaitEvent(0, ev1, 0);

    gemm_k <<<dim3(12, NTOK/128), 256, SMEM_BYTES>>>(0, bq, bk, bv, mask, nullptr, nullptr);
    kv_k   <<<dim3(Bb*Hh, 16), 128>>>();
    y_k    <<<dim3(Bb*Hh, Tt/64), 128>>>();
    style_k<<<NTOK, 128>>>(g2, b2);
    gemm_k <<<dim3(4, NTOK/128), 256, SMEM_BYTES>>>(1, outB, nullptr, nullptr, nullptr, x, out);
}

// round 17
// speedup vs baseline: 1.0972x; 1.0112x over previous
#include <cuda_runtime.h>
#include <cuda_fp16.h>
#include <math.h>
#include <stdint.h>

#define Bb   4
#define Tt   8192
#define Dd   512
#define Hh   8
#define DH   64
#define TEE  2048
#define NTOK (Bb*Tt)

// ---------------- scratch ----------------
__device__ __half g_xn[NTOK*Dd];           // LN(x), fp16
__device__ __half g_hs[NTOK*Dd];           // silu(stylized), fp16
__device__ __half g_qkvT[3*Dd*Dd];         // [1536][512] W^T fp16
__device__ __half g_outT[Dd*Dd];           // [512][512]  W^T fp16
__device__ __half g_qs[NTOK*Dd];           // softmaxed q, fp16
__device__ __half g_ek[NTOK*Dd];           // exp(k), fp16
__device__ __half g_vv[NTOK*Dd];           // masked v, fp16
__device__ __half g_y [NTOK*Dd];           // attention out, fp16
__device__ float g_ksum[Bb*Dd];
__device__ float g_attn[Bb*Hh*DH*DH];
__device__ float g_emb[Bb*2*Dd];

// ---------------- helpers ----------------
__device__ __forceinline__ uint32_t smem_u32(const void* p) {
    uint32_t a;
    asm("{ .reg .u64 t; cvta.to.shared.u64 t, %1; cvt.u32.u64 %0, t; }" : "=r"(a) : "l"(p));
    return a;
}
__device__ __forceinline__ void cp16(void* dst, const void* src) {
    uint32_t d;
    asm("{ .reg .u64 t; cvta.to.shared.u64 t, %1; cvt.u32.u64 %0, t; }" : "=r"(d) : "l"(dst));
    asm volatile("cp.async.cg.shared.global [%0], [%1], 16;" :: "r"(d), "l"(src) : "memory");
}
__device__ __forceinline__ void ldsm4(uint32_t* r, uint32_t addr) {
    asm volatile("ldmatrix.sync.aligned.m8n8.x4.shared.b16 {%0,%1,%2,%3}, [%4];"
        : "=r"(r[0]), "=r"(r[1]), "=r"(r[2]), "=r"(r[3]) : "r"(addr));
}
__device__ __forceinline__ void mma_f16(float* c, const uint32_t* a, const uint32_t* b) {
    asm volatile(
        "mma.sync.aligned.m16n8k16.row.col.f32.f16.f16.f32 "
        "{%0,%1,%2,%3}, {%4,%5,%6,%7}, {%8,%9}, {%0,%1,%2,%3};"
        : "+f"(c[0]), "+f"(c[1]), "+f"(c[2]), "+f"(c[3])
        : "r"(a[0]), "r"(a[1]), "r"(a[2]), "r"(a[3]), "r"(b[0]), "r"(b[1]));
}
__device__ __forceinline__ void mma_tf32(float* c, const uint32_t* a, const uint32_t* b) {
    asm volatile(
        "mma.sync.aligned.m16n8k8.row.col.f32.tf32.tf32.f32 "
        "{%0,%1,%2,%3}, {%4,%5,%6,%7}, {%8,%9}, {%0,%1,%2,%3};"
        : "+f"(c[0]), "+f"(c[1]), "+f"(c[2]), "+f"(c[3])
        : "r"(a[0]), "r"(a[1]), "r"(a[2]), "r"(a[3]), "r"(b[0]), "r"(b[1]));
}

// ---------------- zero accumulators + seed emb with bias ----------------
__global__ void zero_k(const float* __restrict__ embB) {
    int i = blockIdx.x * blockDim.x + threadIdx.x;
    if (i < Bb*Dd) g_ksum[i] = 0.f;
    if (i < Bb*Hh*DH*DH) g_attn[i] = 0.f;
    if (i < Bb*2*Dd) g_emb[i] = embB[i & (2*Dd - 1)];
}

// ---------------- weight transpose + fp16 ----------------
__global__ void wconv_k(const float* __restrict__ Wq, const float* __restrict__ Wk,
                        const float* __restrict__ Wv, const float* __restrict__ Wo) {
    __shared__ float t[32][33];
    int mat = blockIdx.z;
    const float* W = mat == 0 ? Wq : mat == 1 ? Wk : mat == 2 ? Wv : Wo;
    int k0 = blockIdx.y * 32, n0 = blockIdx.x * 32;
    int tx = threadIdx.x, ty = threadIdx.y;
    #pragma unroll
    for (int i = 0; i < 4; i++)
        t[ty + i*8][tx] = W[(size_t)(k0 + ty + i*8)*Dd + n0 + tx];
    __syncthreads();
    __half* dst = (mat < 3) ? g_qkvT : g_outT;
    int nbase = (mat < 3) ? mat*Dd : 0;
    #pragma unroll
    for (int i = 0; i < 4; i++) {
        int n = n0 + ty + i*8, k = k0 + tx;
        dst[(size_t)(nbase + n)*Dd + k] = __float2half_rn(t[tx][ty + i*8]);
    }
}

// ---------------- emb partial: silu(emb_chunk) @ W_chunk, atomic add ----------
__global__ void emb_k(const float* __restrict__ emb,
                      const float* __restrict__ W) {
    __shared__ float se[256];
    int b = blockIdx.x, oc = blockIdx.y, ec = blockIdx.z;
    int tid = threadIdx.x;
    if (tid < 128) {
        #pragma unroll
        for (int i = 0; i < 2; i++) {
            float e = emb[b*TEE + ec*256 + tid*2 + i];
            se[tid*2 + i] = e / (1.f + __expf(-e));
        }
    }
    __syncthreads();
    int o = oc*128 + (tid & 127);
    int eh = (tid >> 7) * 128;
    float acc = 0.f;
    #pragma unroll 4
    for (int e = 0; e < 128; e++)
        acc += se[eh + e] * W[(size_t)(ec*256 + eh + e)*(2*Dd) + o];
    atomicAdd(&g_emb[b*2*Dd + o], acc);
}

// ---------------- LN(x) -> g_xn (fp16); fused single-pass moments ----------
__global__ void ln_k(const float* __restrict__ x,
                     const float* __restrict__ g,
                     const float* __restrict__ be) {
    int tok = blockIdx.x, tid = threadIdx.x;
    float4 v = ((const float4*)(x + (size_t)tok*Dd))[tid];
    float s  = v.x + v.y + v.z + v.w;
    float ss = v.x*v.x + v.y*v.y + v.z*v.z + v.w*v.w;
    __shared__ float r1[4], r2[4];
    for (int o = 16; o; o >>= 1) {
        s  += __shfl_xor_sync(0xffffffffu, s, o);
        ss += __shfl_xor_sync(0xffffffffu, ss, o);
    }
    if ((tid & 31) == 0) { r1[tid >> 5] = s; r2[tid >> 5] = ss; }
    __syncthreads();
    float mu  = (r1[0] + r1[1] + r1[2] + r1[3]) * (1.f / Dd);
    float ex2 = (r2[0] + r2[1] + r2[2] + r2[3]) * (1.f / Dd);
    float rs = rsqrtf(ex2 - mu*mu + 1e-5f);
    float a = v.x - mu, b = v.y - mu, c = v.z - mu, d = v.w - mu;
    float4 gg = ((const float4*)g)[tid], bb = ((const float4*)be)[tid];
    __half2* ph = (__half2*)(g_xn + (size_t)tok*Dd);
    ph[tid*2]   = __halves2half2(__float2half_rn(a*rs*gg.x + bb.x),
                                 __float2half_rn(b*rs*gg.y + bb.y));
    ph[tid*2+1] = __halves2half2(__float2half_rn(c*rs*gg.z + bb.z),
                                 __float2half_rn(d*rs*gg.w + bb.w));
}

// ---------------- fp16 HMMA GEMM: BM=128, BN=128, BK=64, single-sync loop ----
#define AROW 72
#define STG_A (128*AROW)
#define STG_B (128*AROW)
#define STAGE_H (STG_A + STG_B)
#define SMEM_BYTES (3*STAGE_H*2)           // 110592 B -> 2 CTAs/SM

__device__ __forceinline__ void copy_stage(__half* smh, int st, int kc,
    const __half* __restrict__ Ag, const __half* __restrict__ Bg,
    int m0, int n0, int tid)
{
    __half* A = smh + st*STAGE_H;
    __half* B = A + STG_A;
    #pragma unroll
    for (int i = 0; i < 4; i++) {
        int s = tid + i*256;
        int r = s >> 3, c8 = s & 7;
        cp16(A + r*AROW + c8*8, Ag + (size_t)(m0 + r)*Dd + kc*64 + c8*8);
    }
    #pragma unroll
    for (int i = 0; i < 4; i++) {
        int s = tid + i*256;
        int r = s >> 3, c8 = s & 7;
        cp16(B + r*AROW + c8*8, Bg + (size_t)(n0 + r)*Dd + kc*64 + c8*8);
    }
    asm volatile("cp.async.commit_group;" ::: "memory");
}

__global__ __launch_bounds__(256, 2) void gemm_k(
    int mode,                       // 0 = QKV, 1 = OUT
    const float* __restrict__ b0, const float* __restrict__ b1, const float* __restrict__ b2,
    const float* __restrict__ mask, const float* __restrict__ xres, float* __restrict__ outp)
{
    extern __shared__ __half smh[];
    uint32_t smb = smem_u32(smh);
    int tid = threadIdx.x;
    int lane = tid & 31, w = tid >> 5;
    int g = lane >> 2, cq = lane & 3;
    int wm = w >> 1, wn = w & 1;
    int mBase = wm*32, nBase = wn*64;
    int m0 = blockIdx.y * 128;
    int n0 = blockIdx.x * 128;

    const __half* Ag = mode ? g_hs : g_xn;
    const __half* Bg = mode ? g_outT : g_qkvT;

    uint32_t aoff[2], boff[4];
    {
        int ar = lane & 15;
        int ac = (lane >> 4) * 8;
        #pragma unroll
        for (int mt = 0; mt < 2; mt++)
            aoff[mt] = (uint32_t)(((mBase + mt*16 + ar)*AROW + ac) * 2);
        int br = ((lane >> 4) << 3) | (lane & 7);
        int bc = ((lane >> 3) & 1) * 8;
        #pragma unroll
        for (int p = 0; p < 4; p++)
            boff[p] = (uint32_t)(((nBase + p*16 + br)*AROW + bc) * 2 + STG_A*2);
    }

    float acc[2][8][4];
    #pragma unroll
    for (int i = 0; i < 2; i++)
        #pragma unroll
        for (int j = 0; j < 8; j++)
            #pragma unroll
            for (int r = 0; r < 4; r++) acc[i][j][r] = 0.f;

    copy_stage(smh, 0, 0, Ag, Bg, m0, n0, tid);
    copy_stage(smh, 1, 1, Ag, Bg, m0, n0, tid);

    // single-sync mainloop: wait -> sync -> MMA(it) -> issue copy(it+2)
    const int NIT = Dd/64;                 // 8
    for (int it = 0; it < NIT; it++) {
        if (it + 1 < NIT) asm volatile("cp.async.wait_group 1;" ::: "memory");
        else              asm volatile("cp.async.wait_group 0;" ::: "memory");
        __syncthreads();

        uint32_t stageB = smb + (uint32_t)((it%3)*STAGE_H*2);
        #pragma unroll
        for (int k16 = 0; k16 < 4; k16++) {
            uint32_t kb = (uint32_t)(k16*32);
            uint32_t a[2][4], bb[4][4];
            #pragma unroll
            for (int mt = 0; mt < 2; mt++) ldsm4(a[mt], stageB + aoff[mt] + kb);
            #pragma unroll
            for (int p = 0; p < 4; p++)    ldsm4(bb[p], stageB + boff[p] + kb);
            #pragma unroll
            for (int mt = 0; mt < 2; mt++)
                #pragma unroll
                for (int p = 0; p < 4; p++) {
                    mma_f16(acc[mt][2*p],   a[mt], &bb[p][0]);
                    mma_f16(acc[mt][2*p+1], a[mt], &bb[p][2]);
                }
        }
        if (it + 2 < NIT) copy_stage(smh, (it+2)%3, it+2, Ag, Bg, m0, n0, tid);
    }

    // ---------------- register epilogue ----------------
    int region = n0 >> 9;
    const float* bia = (mode == 1) ? b0 : (region == 0 ? b0 : (region == 1 ? b1 : b2));
    int cbase = ((mode == 1) ? n0 : (n0 & 511)) + nBase + cq*2;
    float blo[8], bhi[8];
    #pragma unroll
    for (int nt = 0; nt < 8; nt++) { blo[nt] = bia[cbase + nt*8]; bhi[nt] = bia[cbase + nt*8 + 1]; }

    if (mode == 1) {
        #pragma unroll
        for (int mt = 0; mt < 2; mt++)
            #pragma unroll
            for (int rh = 0; rh < 2; rh++) {
                int m = m0 + mBase + mt*16 + g + rh*8;
                #pragma unroll
                for (int nt = 0; nt < 8; nt++) {
                    size_t off = (size_t)m*Dd + n0 + nBase + nt*8 + cq*2;
                    float2 xr = *(const float2*)(xres + off);
                    float2 o = make_float2(acc[mt][nt][2*rh]   + blo[nt] + xr.x,
                                           acc[mt][nt][2*rh+1] + bhi[nt] + xr.y);
                    *(float2*)(outp + off) = o;
                }
            }
    } else if (region == 0) {
        #pragma unroll
        for (int mt = 0; mt < 2; mt++)
            #pragma unroll
            for (int rh = 0; rh < 2; rh++) {
                int m = m0 + mBase + mt*16 + g + rh*8;
                float v0[8], v1[8];
                float mx = -1e30f;
                #pragma unroll
                for (int nt = 0; nt < 8; nt++) {
                    v0[nt] = acc[mt][nt][2*rh]   + blo[nt];
                    v1[nt] = acc[mt][nt][2*rh+1] + bhi[nt];
                    mx = fmaxf(mx, fmaxf(v0[nt], v1[nt]));
                }
                mx = fmaxf(mx, __shfl_xor_sync(0xffffffffu, mx, 1));
                mx = fmaxf(mx, __shfl_xor_sync(0xffffffffu, mx, 2));
                float s = 0.f;
                #pragma unroll
                for (int nt = 0; nt < 8; nt++) {
                    v0[nt] = __expf(v0[nt] - mx); v1[nt] = __expf(v1[nt] - mx);
                    s += v0[nt] + v1[nt];
                }
                s += __shfl_xor_sync(0xffffffffu, s, 1);
                s += __shfl_xor_sync(0xffffffffu, s, 2);
                float inv = 1.f / s;
                #pragma unroll
                for (int nt = 0; nt < 8; nt++)
                    *(__half2*)(g_qs + (size_t)m*Dd + cbase + nt*8) =
                        __floats2half2_rn(v0[nt]*inv, v1[nt]*inv);
            }
    } else if (region == 1) {
        float cs0[8] = {}, cs1[8] = {};
        #pragma unroll
        for (int mt = 0; mt < 2; mt++)
            #pragma unroll
            for (int rh = 0; rh < 2; rh++) {
                int m = m0 + mBase + mt*16 + g + rh*8;
                float madd = (1.f - mask[m]) * (-1e6f);
                #pragma unroll
                for (int nt = 0; nt < 8; nt++) {
                    float e0 = __expf(acc[mt][nt][2*rh]   + blo[nt] + madd);
                    float e1 = __expf(acc[mt][nt][2*rh+1] + bhi[nt] + madd);
                    __half2 h2 = __floats2half2_rn(e0, e1);
                    *(__half2*)(g_ek + (size_t)m*Dd + cbase + nt*8) = h2;
                    float2 hf = __half22float2(h2);
                    cs0[nt] += hf.x; cs1[nt] += hf.y;
                }
            }
        #pragma unroll
        for (int o = 4; o <= 16; o <<= 1)
            #pragma unroll
            for (int nt = 0; nt < 8; nt++) {
                cs0[nt] += __shfl_xor_sync(0xffffffffu, cs0[nt], o);
                cs1[nt] += __shfl_xor_sync(0xffffffffu, cs1[nt], o);
            }
        if (lane < 4) {
            int batch = m0 >> 13;
            #pragma unroll
            for (int nt = 0; nt < 8; nt++) {
                atomicAdd(&g_ksum[batch*Dd + cbase + nt*8],     cs0[nt]);
                atomicAdd(&g_ksum[batch*Dd + cbase + nt*8 + 1], cs1[nt]);
            }
        }
    } else {
        #pragma unroll
        for (int mt = 0; mt < 2; mt++)
            #pragma unroll
            for (int rh = 0; rh < 2; rh++) {
                int m = m0 + mBase + mt*16 + g + rh*8;
                float mv = mask[m];
                #pragma unroll
                for (int nt = 0; nt < 8; nt++)
                    *(__half2*)(g_vv + (size_t)m*Dd + cbase + nt*8) =
                        __floats2half2_rn((acc[mt][nt][2*rh]   + blo[nt])*mv,
                                          (acc[mt][nt][2*rh+1] + bhi[nt])*mv);
            }
    }
}

// ---------------- KV state (tf32 tensor, fp16 inputs) ----------------
__global__ __launch_bounds__(128) void kv_k() {
    __shared__ float Es[64][72];
    __shared__ float Vs[64][72];
    int bh = blockIdx.x; int b = bh >> 3; int h = bh & 7;
    int t0 = b*Tt + blockIdx.y * 512;
    int tid = threadIdx.x;
    int lane = tid & 31, w = tid >> 5;
    int g = lane >> 2, cq = lane & 3;
    int mBase = w * 16;

    float acc[8][4];
    #pragma unroll
    for (int i = 0; i < 8; i++)
        #pragma unroll
        for (int r = 0; r < 4; r++) acc[i][r] = 0.f;

    for (int tile = 0; tile < 8; tile++) {
        #pragma unroll
        for (int i = 0; i < 8; i++) {
            int s = tid + i*128;
            int r = s >> 4, c4 = s & 15;
            size_t base = (size_t)(t0 + tile*64 + r)*Dd + h*DH + c4*4;
            const __half2* pe = (const __half2*)(g_ek + base);
            const __half2* pv = (const __half2*)(g_vv + base);
            float2 e0 = __half22float2(pe[0]), e1 = __half22float2(pe[1]);
            float2 v0 = __half22float2(pv[0]), v1 = __half22float2(pv[1]);
            *(float4*)&Es[r][c4*4] = make_float4(e0.x, e0.y, e1.x, e1.y);
            *(float4*)&Vs[r][c4*4] = make_float4(v0.x, v0.y, v1.x, v1.y);
        }
        __syncthreads();
        #pragma unroll
        for (int k8 = 0; k8 < 8; k8++) {
            int kk = k8*8;
            uint32_t a[4], bfr[8][2];
            a[0] = __float_as_uint(Es[kk+cq][mBase+g]);
            a[1] = __float_as_uint(Es[kk+cq][mBase+g+8]);
            a[2] = __float_as_uint(Es[kk+cq+4][mBase+g]);
            a[3] = __float_as_uint(Es[kk+cq+4][mBase+g+8]);
            #pragma unroll
            for (int nt = 0; nt < 8; nt++) {
                bfr[nt][0] = __float_as_uint(Vs[kk+cq][nt*8+g]);
                bfr[nt][1] = __float_as_uint(Vs[kk+cq+4][nt*8+g]);
            }
            #pragma unroll
            for (int nt = 0; nt < 8; nt++)
                mma_tf32(acc[nt], a, bfr[nt]);
        }
        __syncthreads();
    }
    float* A = g_attn + (size_t)bh*DH*DH;
    #pragma unroll
    for (int nt = 0; nt < 8; nt++) {
        int n = nt*8 + cq*2;
        atomicAdd(&A[(mBase+g)*DH + n],     acc[nt][0]);
        atomicAdd(&A[(mBase+g)*DH + n+1],   acc[nt][1]);
        atomicAdd(&A[(mBase+g+8)*DH + n],   acc[nt][2]);
        atomicAdd(&A[(mBase+g+8)*DH + n+1], acc[nt][3]);
    }
}

// ---------------- y = q_h @ (attn_h / ksum) (tf32 tensor, fp16 in/out) --------
__global__ __launch_bounds__(128) void y_k() {
    __shared__ float Qs[64][68];
    __shared__ float Ahs[64][72];
    int bh = blockIdx.x; int b = bh >> 3; int h = bh & 7;
    int t0 = b*Tt + blockIdx.y * 64;
    int tid = threadIdx.x;
    int lane = tid & 31, w = tid >> 5;
    int g = lane >> 2, cq = lane & 3;
    int mBase = w * 16;

    {
        const float* A  = g_attn + (size_t)bh*DH*DH;
        const float* ks = g_ksum + b*Dd + h*DH;
        #pragma unroll
        for (int i = 0; i < 8; i++) {
            int s = tid + i*128;
            int r = s >> 4, c4 = s & 15;
            float rk = 1.f / ks[r];
            float4 a = *(const float4*)(A + r*DH + c4*4);
            a.x *= rk; a.y *= rk; a.z *= rk; a.w *= rk;
            *(float4*)&Ahs[r][c4*4] = a;
            const __half2* pq = (const __half2*)(g_qs + (size_t)(t0 + r)*Dd + h*DH + c4*4);
            float2 q0 = __half22float2(pq[0]), q1 = __half22float2(pq[1]);
            *(float4*)&Qs[r][c4*4] = make_float4(q0.x, q0.y, q1.x, q1.y);
        }
    }
    __syncthreads();

    float acc[8][4];
    #pragma unroll
    for (int i = 0; i < 8; i++)
        #pragma unroll
        for (int r = 0; r < 4; r++) acc[i][r] = 0.f;

    #pragma unroll
    for (int k8 = 0; k8 < 8; k8++) {
        int kk = k8*8;
        uint32_t a[4], bfr[8][2];
        a[0] = __float_as_uint(Qs[mBase+g][kk+cq]);
        a[1] = __float_as_uint(Qs[mBase+g+8][kk+cq]);
        a[2] = __float_as_uint(Qs[mBase+g][kk+cq+4]);
        a[3] = __float_as_uint(Qs[mBase+g+8][kk+cq+4]);
        #pragma unroll
        for (int nt = 0; nt < 8; nt++) {
            bfr[nt][0] = __float_as_uint(Ahs[kk+cq][nt*8+g]);
            bfr[nt][1] = __float_as_uint(Ahs[kk+cq+4][nt*8+g]);
        }
        #pragma unroll
        for (int nt = 0; nt < 8; nt++)
            mma_tf32(acc[nt], a, bfr[nt]);
    }

    #pragma unroll
    for (int nt = 0; nt < 8; nt++) {
        int n = h*DH + nt*8 + cq*2;
        size_t r0 = (size_t)(t0 + mBase + g)*Dd + n;
        size_t r1 = (size_t)(t0 + mBase + g + 8)*Dd + n;
        *(__half2*)(g_y + r0) = __floats2half2_rn(acc[nt][0], acc[nt][1]);
        *(__half2*)(g_y + r1) = __floats2half2_rn(acc[nt][2], acc[nt][3]);
    }
}

// ---------------- stylize + silu -> g_hs; fused single-pass moments ---------
__global__ void style_k(const float* __restrict__ g2, const float* __restrict__ b2) {
    int tok = blockIdx.x, tid = threadIdx.x;
    int b = tok >> 13;
    const __half2* py = (const __half2*)(g_y + (size_t)tok*Dd);
    float2 y01 = __half22float2(py[tid*2]);
    float2 y23 = __half22float2(py[tid*2+1]);
    float s  = y01.x + y01.y + y23.x + y23.y;
    float ss = y01.x*y01.x + y01.y*y01.y + y23.x*y23.x + y23.y*y23.y;
    __shared__ float r1[4], r2[4];
    for (int o = 16; o; o >>= 1) {
        s  += __shfl_xor_sync(0xffffffffu, s, o);
        ss += __shfl_xor_sync(0xffffffffu, ss, o);
    }
    if ((tid & 31) == 0) { r1[tid >> 5] = s; r2[tid >> 5] = ss; }
    __syncthreads();
    float mu  = (r1[0] + r1[1] + r1[2] + r1[3]) * (1.f / Dd);
    float ex2 = (r2[0] + r2[1] + r2[2] + r2[3]) * (1.f / Dd);
    float rs = rsqrtf(ex2 - mu*mu + 1e-5f);
    float a = y01.x - mu, bb_ = y01.y - mu, c = y23.x - mu, d = y23.y - mu;
    float4 gg = ((const float4*)g2)[tid], bt = ((const float4*)b2)[tid];
    float4 sc = ((const float4*)(g_emb + b*2*Dd))[tid];
    float4 sh = ((const float4*)(g_emb + b*2*Dd + Dd))[tid];
    float h0 = (a  *rs*gg.x + bt.x)*(1.f + sc.x) + sh.x;
    float h1 = (bb_*rs*gg.y + bt.y)*(1.f + sc.y) + sh.y;
    float h2 = (c  *rs*gg.z + bt.z)*(1.f + sc.z) + sh.z;
    float h3 = (d  *rs*gg.w + bt.w)*(1.f + sc.w) + sh.w;
    h0 = h0 / (1.f + __expf(-h0));
    h1 = h1 / (1.f + __expf(-h1));
    h2 = h2 / (1.f + __expf(-h2));
    h3 = h3 / (1.f + __expf(-h3));
    __half2* ph = (__half2*)(g_hs + (size_t)tok*Dd);
    ph[tid*2]   = __halves2half2(__float2half_rn(h0), __float2half_rn(h1));
    ph[tid*2+1] = __halves2half2(__float2half_rn(h2), __float2half_rn(h3));
}

// ---------------- launch ----------------
extern "C" void kernel_launch(void* const* d_in, const int* in_sizes, int n_in,
                              void* d_out, int out_size) {
    const float* x     = (const float*)d_in[0];
    const float* emb   = (const float*)d_in[1];
    const float* mask  = (const float*)d_in[2];
    const float* gamma = (const float*)d_in[3];
    const float* beta  = (const float*)d_in[4];
    const float* Wq    = (const float*)d_in[5];
    const float* bq    = (const float*)d_in[6];
    const float* Wk    = (const float*)d_in[7];
    const float* bk    = (const float*)d_in[8];
    const float* Wv    = (const float*)d_in[9];
    const float* bv    = (const float*)d_in[10];
    const float* embW  = (const float*)d_in[11];
    const float* embB  = (const float*)d_in[12];
    const float* g2    = (const float*)d_in[13];
    const float* b2    = (const float*)d_in[14];
    const float* outW  = (const float*)d_in[15];
    const float* outB  = (const float*)d_in[16];
    float* out = (float*)d_out;

    static int inited = 0;
    static cudaStream_t s2;
    static cudaEvent_t ev0, ev1;
    if (!inited) {
        cudaFuncSetAttribute(gemm_k, cudaFuncAttributeMaxDynamicSharedMemorySize, SMEM_BYTES);
        cudaStreamCreateWithFlags(&s2, cudaStreamNonBlocking);
        cudaEventCreateWithFlags(&ev0, cudaEventDisableTiming);
        cudaEventCreateWithFlags(&ev1, cudaEventDisableTiming);
        inited = 1;
    }

    // fork: {wconv, emb} on s2 || {ln} on main; join before QKV GEMM
    zero_k <<<512, 256>>>(embB);
    cudaEventRecord(ev0, 0);
    cudaStreamWaitEvent(s2, ev0, 0);
    wconv_k<<<dim3(16, 16, 4), dim3(32, 8), 0, s2>>>(Wq, Wk, Wv, outW);
    emb_k  <<<dim3(Bb, 8, 8), 256, 0, s2>>>(emb, embW);
    cudaEventRecord(ev1, s2);
    ln_k   <<<NTOK, 128>>>(x, gamma, beta);
    cudaStreamWaitEvent(0, ev1, 0);

    gemm_k <<<dim3(12, NTOK/128), 256, SMEM_BYTES>>>(0, bq, bk, bv, mask, nullptr, nullptr);
    kv_k   <<<dim3(Bb*Hh, 16), 128>>>();
    y_k    <<<dim3(Bb*Hh, Tt/64), 128>>>();
    style_k<<<NTOK, 128>>>(g2, b2);
    gemm_k <<<dim3(4, NTOK/128), 256, SMEM_BYTES>>>(1, outB, nullptr, nullptr, nullptr, x, out);
}